// round 3
// baseline (speedup 1.0000x reference)
#include <cuda_runtime.h>

#define N_FFT  4096
#define LOG2N  12
#define F_LEN  2049
#define B_SZ   32
#define C_SZ   8
#define E_NUM  8
#define NROW   (B_SZ * C_SZ)     // 256
#define NT     512

// ---------------- device scratch (no allocations allowed) ----------------
__device__ float2 g_freq[NROW * F_LEN];     // spectrum per (b,c)
__device__ float  g_gate[B_SZ * F_LEN];     // gating input [B, F]
__device__ float  g_mean[NROW];
__device__ float  g_std[NROW];
__device__ float  g_h[B_SZ * F_LEN];        // hidden layer
__device__ float  g_scores[B_SZ * E_NUM];
__device__ int    g_idx[E_NUM + 1];
__device__ float  g_dummy[16 + B_SZ * E_NUM]; // sink if out buffer is small

// ---------------- helpers ----------------
__device__ __forceinline__ int brev12(int i) { return (int)(__brev((unsigned)i) >> 20); }

__device__ __forceinline__ float2 cmul(float2 a, float2 b) {
    return make_float2(a.x * b.x - a.y * b.y, a.x * b.y + a.y * b.x);
}

// twiddle table: tw[k] = exp(-2*pi*i*k/N), k in [0, N/4)
__device__ __forceinline__ void fill_tw(float2* tw, int tid, int nt) {
    for (int k = tid; k < N_FFT / 4; k += nt) {
        float s, c;
        sincospif(-(float)k / (float)(N_FFT / 2), &s, &c);
        tw[k] = make_float2(c, s);
    }
}

template <bool INV>
__device__ __forceinline__ float2 twget(const float2* tw, int idx) {
    // idx in [0, N/2)
    float2 t;
    if (idx < N_FFT / 4) {
        t = tw[idx];
    } else {
        float2 u = tw[idx - N_FFT / 4];       // multiply by exp(-i*pi/2) = -i
        t = make_float2(u.y, -u.x);
    }
    if (INV) t.y = -t.y;
    return t;
}

// in-place radix-2 DIT FFT on shared array a[N_FFT]; input bit-reversed, output natural
template <bool INV>
__device__ void fft_shared(float2* a, const float2* tw, int tid) {
    #pragma unroll
    for (int s = 0; s < LOG2N; s++) {
        int half = 1 << s;
        int shift = LOG2N - 1 - s;   // twiddle index = j << shift
        for (int t = tid; t < N_FFT / 2; t += NT) {
            int j = t & (half - 1);
            int i = ((t >> s) << (s + 1)) + j;
            float2 w = twget<INV>(tw, j << shift);
            float2 u = a[i];
            float2 v = cmul(a[i + half], w);
            a[i]        = make_float2(u.x + v.x, u.y + v.y);
            a[i + half] = make_float2(u.x - v.x, u.y - v.y);
        }
        __syncthreads();
    }
}

// ---------------- kernel 1: norm + forward FFT per (b,c) row ----------------
__global__ __launch_bounds__(NT) void k1_norm_fft(const float* __restrict__ x) {
    __shared__ float2 a[N_FFT];          // 32 KB
    __shared__ float2 tw[N_FFT / 4];     // 8 KB
    __shared__ float  red[NT];           // 2 KB

    int row = blockIdx.x;
    int tid = threadIdx.x;
    const float* xr = x + (size_t)row * N_FFT;

    fill_tw(tw, tid, NT);

    float s = 0.f, ss = 0.f;
    for (int k = tid; k < N_FFT; k += NT) {
        float v = xr[k];
        a[k] = make_float2(v, 0.f);
        s += v; ss += v * v;
    }
    red[tid] = s; __syncthreads();
    for (int o = NT / 2; o > 0; o >>= 1) { if (tid < o) red[tid] += red[tid + o]; __syncthreads(); }
    float sum = red[0]; __syncthreads();
    red[tid] = ss; __syncthreads();
    for (int o = NT / 2; o > 0; o >>= 1) { if (tid < o) red[tid] += red[tid + o]; __syncthreads(); }
    float sumsq = red[0]; __syncthreads();

    float mean = sum * (1.0f / N_FFT);
    float var  = (sumsq - sum * mean) * (1.0f / (N_FFT - 1)) + 1e-5f;
    float stdv = sqrtf(var);
    float inv  = 1.0f / stdv;
    if (tid == 0) { g_mean[row] = mean; g_std[row] = stdv; }

    for (int k = tid; k < N_FFT; k += NT) a[k].x = (a[k].x - mean) * inv;
    __syncthreads();
    // bit-reversal permutation (disjoint swap pairs)
    for (int k = tid; k < N_FFT; k += NT) {
        int r = brev12(k);
        if (r > k) { float2 t = a[k]; a[k] = a[r]; a[r] = t; }
    }
    __syncthreads();

    fft_shared<false>(a, tw, tid);

    float2* fr = g_freq + (size_t)row * F_LEN;
    for (int f = tid; f < F_LEN; f += NT) fr[f] = a[f];
}

// ---------------- kernel 1b: gating input = mean_c |freq| ----------------
__global__ void k1b_gate() {
    int i = blockIdx.x * blockDim.x + threadIdx.x;   // over B_SZ * F_LEN
    if (i >= B_SZ * F_LEN) return;
    int b = i / F_LEN;
    int f = i - b * F_LEN;
    float acc = 0.f;
    #pragma unroll
    for (int c = 0; c < C_SZ; c++) {
        float2 v = g_freq[(size_t)(b * C_SZ + c) * F_LEN + f];
        acc += sqrtf(v.x * v.x + v.y * v.y);
    }
    g_gate[i] = acc * (1.0f / C_SZ);
}

// ---------------- kernel 2a: boundaries / band edges ----------------
__global__ void k2a_bounds(const float* __restrict__ raw, float* __restrict__ out_bounds) {
    float b[E_NUM - 1];
    for (int i = 0; i < E_NUM - 1; i++) b[i] = 1.0f / (1.0f + expf(-raw[i]));
    for (int i = 1; i < E_NUM - 1; i++) {           // insertion sort
        float v = b[i]; int j = i - 1;
        while (j >= 0 && b[j] > v) { b[j + 1] = b[j]; j--; }
        b[j + 1] = v;
    }
    float bd[E_NUM + 1];
    bd[0] = 0.f;
    for (int i = 0; i < E_NUM - 1; i++) bd[i + 1] = b[i];
    bd[E_NUM] = 1.f;
    for (int i = 0; i <= E_NUM; i++) {
        out_bounds[i] = bd[i];
        g_idx[i] = (int)floorf(bd[i] * (float)F_LEN);
    }
    g_idx[E_NUM] = F_LEN;
}

// ---------------- kernel 2b: h = relu(G @ W1^T + b1) ----------------
__global__ __launch_bounds__(1024) void k2b_gemm1(const float* __restrict__ W1,
                                                  const float* __restrict__ b1) {
    __shared__ float Gs[32][33];
    __shared__ float Ws[32][33];
    int tx = threadIdx.x;   // output column (local)
    int ty = threadIdx.y;   // batch
    int o  = blockIdx.x * 32 + tx;
    float acc = 0.f;
    for (int k0 = 0; k0 < F_LEN; k0 += 32) {
        int k = k0 + tx;
        Gs[ty][tx] = (k < F_LEN) ? g_gate[ty * F_LEN + k] : 0.f;
        int orow = blockIdx.x * 32 + ty;
        Ws[ty][tx] = (orow < F_LEN && k < F_LEN) ? W1[(size_t)orow * F_LEN + k] : 0.f;
        __syncthreads();
        #pragma unroll
        for (int kk = 0; kk < 32; kk++) acc = fmaf(Gs[ty][kk], Ws[tx][kk], acc);
        __syncthreads();
    }
    if (o < F_LEN) g_h[ty * F_LEN + o] = fmaxf(acc + b1[o], 0.f);
}

// ---------------- kernel 2c: logits + softmax ----------------
__global__ __launch_bounds__(256) void k2c_gate(const float* __restrict__ W2,
                                                const float* __restrict__ b2,
                                                float* __restrict__ out_scores) {
    __shared__ float red[256];
    __shared__ float logits[E_NUM];
    int b = blockIdx.x, tid = threadIdx.x;
    float acc[E_NUM];
    #pragma unroll
    for (int e = 0; e < E_NUM; e++) acc[e] = 0.f;
    for (int f = tid; f < F_LEN; f += 256) {
        float hv = g_h[b * F_LEN + f];
        #pragma unroll
        for (int e = 0; e < E_NUM; e++) acc[e] = fmaf(hv, W2[e * F_LEN + f], acc[e]);
    }
    for (int e = 0; e < E_NUM; e++) {
        red[tid] = acc[e]; __syncthreads();
        for (int o = 128; o > 0; o >>= 1) { if (tid < o) red[tid] += red[tid + o]; __syncthreads(); }
        if (tid == 0) logits[e] = red[0] + b2[e];
        __syncthreads();
    }
    if (tid == 0) {
        float mx = logits[0];
        for (int e = 1; e < E_NUM; e++) mx = fmaxf(mx, logits[e]);
        float sm = 0.f, ex[E_NUM];
        for (int e = 0; e < E_NUM; e++) { ex[e] = expf(logits[e] - mx); sm += ex[e]; }
        float is = 1.0f / sm;
        for (int e = 0; e < E_NUM; e++) {
            float v = ex[e] * is;
            g_scores[b * E_NUM + e] = v;
            out_scores[b * E_NUM + e] = v;
        }
    }
}

// ---------------- kernel 3: expert band irfft ----------------
__global__ __launch_bounds__(NT) void k3_expert(float* __restrict__ out_exp) {
    __shared__ float2 a[N_FFT];
    __shared__ float2 tw[N_FFT / 4];
    __shared__ int s_lo, s_hi;

    int blk = blockIdx.x;                 // b*64 + e*8 + c
    int c = blk & 7;
    int e = (blk >> 3) & 7;
    int b = blk >> 6;
    int row = b * C_SZ + c;
    int tid = threadIdx.x;

    if (tid == 0) { s_lo = g_idx[e]; s_hi = g_idx[e + 1]; }
    fill_tw(tw, tid, NT);
    __syncthreads();
    int lo = s_lo, hi = s_hi;

    const float2* fr = g_freq + (size_t)row * F_LEN;
    for (int k = tid; k < N_FFT; k += NT) {
        int kk = (k <= N_FFT / 2) ? k : (N_FFT - k);
        float2 v = make_float2(0.f, 0.f);
        if (kk >= lo && kk < hi) {
            v = fr[kk];
            if (k > N_FFT / 2) v.y = -v.y;   // hermitian extension
        }
        a[brev12(k)] = v;
    }
    __syncthreads();

    fft_shared<true>(a, tw, tid);

    float* o = out_exp + (size_t)blk * N_FFT;
    const float sc = 1.0f / N_FFT;
    for (int k = tid; k < N_FFT; k += NT) o[k] = a[k].x * sc;
}

// ---------------- kernel 4: gated combine irfft + denorm ----------------
__global__ __launch_bounds__(NT) void k4_combined(float* __restrict__ out_comb) {
    __shared__ float2 a[N_FFT];
    __shared__ float2 tw[N_FFT / 4];
    __shared__ int   s_idx[E_NUM + 1];
    __shared__ float s_g[E_NUM];

    int row = blockIdx.x;
    int b = row / C_SZ;
    int tid = threadIdx.x;

    if (tid < E_NUM + 1) s_idx[tid] = g_idx[tid];
    if (tid >= 32 && tid < 32 + E_NUM) s_g[tid - 32] = g_scores[b * E_NUM + (tid - 32)];
    fill_tw(tw, tid, NT);
    __syncthreads();

    const float2* fr = g_freq + (size_t)row * F_LEN;
    for (int k = tid; k < N_FFT; k += NT) {
        int kk = (k <= N_FFT / 2) ? k : (N_FFT - k);
        int e = 0;
        while (e < E_NUM - 1 && kk >= s_idx[e + 1]) e++;
        float gsc = s_g[e];
        float2 v = fr[kk];
        float vy = (k > N_FFT / 2) ? -v.y : v.y;
        a[brev12(k)] = make_float2(v.x * gsc, vy * gsc);
    }
    __syncthreads();

    fft_shared<true>(a, tw, tid);

    float mean = g_mean[row], stdv = g_std[row];
    float* o = out_comb + (size_t)row * N_FFT;
    const float sc = 1.0f / N_FFT;
    for (int k = tid; k < N_FFT; k += NT) o[k] = fmaf(a[k].x * sc, stdv, mean);
}

// ---------------- launch ----------------
extern "C" void kernel_launch(void* const* d_in, const int* in_sizes, int n_in,
                              void* d_out, int out_size) {
    const float* x   = (const float*)d_in[0];
    const float* raw = (const float*)d_in[1];
    const float* W1  = (const float*)d_in[2];
    const float* b1  = (const float*)d_in[3];
    const float* W2  = (const float*)d_in[4];
    const float* b2  = (const float*)d_in[5];
    float* out = (float*)d_out;

    const int comb_n   = B_SZ * C_SZ * N_FFT;                 // 1,048,576
    const int bounds_n = E_NUM + 1;                           // 9
    const int scores_n = B_SZ * E_NUM;                        // 256
    const int exp_n    = B_SZ * E_NUM * C_SZ * N_FFT;         // 8,388,608
    const int total_n  = comb_n + bounds_n + scores_n + exp_n;

    bool full = (out_size >= total_n);

    float* out_comb   = out;
    float* out_bounds;
    float* out_scores;
    float* out_exp = nullptr;

    if (full) {
        out_bounds = out + comb_n;
        out_scores = out_bounds + bounds_n;
        out_exp    = out_scores + scores_n;
    } else {
        // defensive: small output buffer -> only combined; sinks for the rest
        cudaGetSymbolAddress((void**)&out_bounds, g_dummy);
        out_scores = out_bounds + 16;
    }

    k1_norm_fft<<<NROW, NT>>>(x);
    k1b_gate<<<(B_SZ * F_LEN + 255) / 256, 256>>>();
    k2a_bounds<<<1, 1>>>(raw, out_bounds);
    {
        dim3 blk(32, 32);
        k2b_gemm1<<<(F_LEN + 31) / 32, blk>>>(W1, b1);
    }
    k2c_gate<<<B_SZ, 256>>>(W2, b2, out_scores);
    if (full) {
        k3_expert<<<B_SZ * E_NUM * C_SZ, NT>>>(out_exp);
    }
    k4_combined<<<NROW, NT>>>(out_comb);
}

// round 5
// speedup vs baseline: 2.0816x; 2.0816x over previous
#include <cuda_runtime.h>

#define N_FFT  4096
#define M_FFT  2048
#define LOG2M  11
#define F_LEN  2049
#define B_SZ   32
#define C_SZ   8
#define E_NUM  8
#define NROW   (B_SZ * C_SZ)     // 256
#define NTF    256               // threads for FFT kernels
#define OSPAN  2112              // 33 * 64
#define KSPL   8

// ---------------- device scratch (no allocations allowed) ----------------
__device__ float2 g_freq[NROW * F_LEN];     // spectrum per (b,c)
__device__ float  g_gate[B_SZ * F_LEN];     // gating input [B, F]
__device__ float  g_mean[NROW];
__device__ float  g_std[NROW];
__device__ float  g_h[B_SZ * F_LEN];        // hidden layer
__device__ float  g_scores[B_SZ * E_NUM];
__device__ int    g_idx[E_NUM + 1];
__device__ float  g_part[KSPL][B_SZ][OSPAN];
__device__ float  g_dummy[16 + B_SZ * E_NUM];

// ---------------- helpers ----------------
__device__ __forceinline__ int brev11(int i) { return (int)(__brev((unsigned)i) >> 21); }

__device__ __forceinline__ float2 cmul(float2 a, float2 b) {
    return make_float2(a.x * b.x - a.y * b.y, a.x * b.y + a.y * b.x);
}

// tw table holds e^{-2*pi*i*k/4096} for k in [0,1024)
__device__ __forceinline__ void fill_tw(float2* tw, int tid) {
    for (int k = tid; k < 1024; k += NTF) {
        float s, c;
        sincospif(-(float)k / 2048.0f, &s, &c);
        tw[k] = make_float2(c, s);
    }
}

// e^{-2*pi*i*k/4096} for k in [0,2048)
__device__ __forceinline__ float2 w4096(const float2* tw, int k) {
    if (k < 1024) return tw[k];
    float2 u = tw[k - 1024];                 // * exp(-i*pi/2) = -i
    return make_float2(u.y, -u.x);
}

// in-place radix-2 DIT FFT, length 2048; input bit-reversed, output natural
template <bool INV>
__device__ void fft2048(float2* a, const float2* tw, int tid) {
    #pragma unroll
    for (int s = 0; s < LOG2M; s++) {
        int half = 1 << s;
        #pragma unroll 4
        for (int t = tid; t < M_FFT / 2; t += NTF) {
            int j = t & (half - 1);
            int i = ((t >> s) << (s + 1)) + j;
            float2 w = w4096(tw, j << (LOG2M - s));   // e^{-2pi i j / (2*half)}
            if (INV) w.y = -w.y;
            float2 u = a[i];
            float2 v = cmul(a[i + half], w);
            a[i]        = make_float2(u.x + v.x, u.y + v.y);
            a[i + half] = make_float2(u.x - v.x, u.y - v.y);
        }
        __syncthreads();
    }
}

// ---------------- kernel 1: norm + forward rfft via half-length trick ----------------
__global__ __launch_bounds__(NTF, 8) void k1_norm_fft(const float* __restrict__ x) {
    __shared__ float2 a[M_FFT];       // 16 KB : packed z[n] = xn[2n] + i xn[2n+1]
    __shared__ float2 tw[1024];       // 8 KB
    __shared__ float  red[16];

    int row = blockIdx.x;
    int tid = threadIdx.x;
    int lane = tid & 31, wid = tid >> 5;

    fill_tw(tw, tid);

    const float4* xr = (const float4*)(x + (size_t)row * N_FFT);
    float s = 0.f, ss = 0.f;
    for (int i = tid; i < N_FFT / 4; i += NTF) {
        float4 v = xr[i];
        a[2 * i]     = make_float2(v.x, v.y);
        a[2 * i + 1] = make_float2(v.z, v.w);
        s  += (v.x + v.y) + (v.z + v.w);
        ss += v.x * v.x + v.y * v.y + v.z * v.z + v.w * v.w;
    }
    #pragma unroll
    for (int o = 16; o; o >>= 1) {
        s  += __shfl_xor_sync(0xffffffffu, s, o);
        ss += __shfl_xor_sync(0xffffffffu, ss, o);
    }
    if (lane == 0) { red[wid] = s; red[wid + 8] = ss; }
    __syncthreads();
    float sum = 0.f, sumsq = 0.f;
    #pragma unroll
    for (int i = 0; i < 8; i++) { sum += red[i]; sumsq += red[8 + i]; }

    float mean = sum * (1.0f / N_FFT);
    float var  = (sumsq - sum * mean) * (1.0f / (N_FFT - 1)) + 1e-5f;
    float stdv = sqrtf(var);
    float inv  = 1.0f / stdv;
    if (tid == 0) { g_mean[row] = mean; g_std[row] = stdv; }
    __syncthreads();

    // normalize + bit-reversal permutation (disjoint swap pairs)
    for (int n = tid; n < M_FFT; n += NTF) {
        int r = brev11(n);
        if (r > n) {
            float2 u = a[n], v = a[r];
            a[n] = make_float2((v.x - mean) * inv, (v.y - mean) * inv);
            a[r] = make_float2((u.x - mean) * inv, (u.y - mean) * inv);
        } else if (r == n) {
            float2 u = a[n];
            a[n] = make_float2((u.x - mean) * inv, (u.y - mean) * inv);
        }
    }
    __syncthreads();

    fft2048<false>(a, tw, tid);

    // unpack: X[k] = (P - i*w*Q)/2, P = Z[k]+conj(Z[M-k]), Q = Z[k]-conj(Z[M-k])
    float2* fr = g_freq + (size_t)row * F_LEN;
    for (int k = tid; k < M_FFT; k += NTF) {
        float2 Zk = a[k];
        float2 Zm = a[(M_FFT - k) & (M_FFT - 1)];
        float2 P = make_float2(Zk.x + Zm.x, Zk.y - Zm.y);
        float2 Q = make_float2(Zk.x - Zm.x, Zk.y + Zm.y);
        float2 w = w4096(tw, k);
        float2 t = cmul(w, Q);                      // w*Q ; X = (P - i*t)/2
        fr[k] = make_float2(0.5f * (P.x + t.y), 0.5f * (P.y - t.x));
    }
    if (tid == 0) fr[M_FFT] = make_float2(a[0].x - a[0].y, 0.f);
}

// ---------------- kernel 1b: gating input = mean_c |freq| ----------------
__global__ void k1b_gate() {
    int i = blockIdx.x * blockDim.x + threadIdx.x;
    if (i >= B_SZ * F_LEN) return;
    int b = i / F_LEN;
    int f = i - b * F_LEN;
    float acc = 0.f;
    #pragma unroll
    for (int c = 0; c < C_SZ; c++) {
        float2 v = g_freq[(size_t)(b * C_SZ + c) * F_LEN + f];
        acc += sqrtf(v.x * v.x + v.y * v.y);
    }
    g_gate[i] = acc * (1.0f / C_SZ);
}

// ---------------- kernel 2a: boundaries / band edges ----------------
__global__ void k2a_bounds(const float* __restrict__ raw, float* __restrict__ out_bounds) {
    float b[E_NUM - 1];
    for (int i = 0; i < E_NUM - 1; i++) b[i] = 1.0f / (1.0f + expf(-raw[i]));
    for (int i = 1; i < E_NUM - 1; i++) {
        float v = b[i]; int j = i - 1;
        while (j >= 0 && b[j] > v) { b[j + 1] = b[j]; j--; }
        b[j + 1] = v;
    }
    float bd[E_NUM + 1];
    bd[0] = 0.f;
    for (int i = 0; i < E_NUM - 1; i++) bd[i + 1] = b[i];
    bd[E_NUM] = 1.f;
    for (int i = 0; i <= E_NUM; i++) {
        out_bounds[i] = bd[i];
        g_idx[i] = (int)floorf(bd[i] * (float)F_LEN);
    }
    g_idx[E_NUM] = F_LEN;
}

// ---------------- kernel 2b: partial GEMM h_part = G @ W1^T (K-split) ----------------
__global__ __launch_bounds__(256) void k2b_part(const float* __restrict__ W1) {
    __shared__ float Gs[32][33];
    __shared__ float Ws[64][33];
    int t  = threadIdx.x;
    int tx = t & 15, ty = t >> 4;
    int oBase = blockIdx.x * 64;
    int kBase = blockIdx.y * 257;
    int kEnd  = min(kBase + 257, F_LEN);

    float acc[2][4] = {};
    for (int k0 = kBase; k0 < kEnd; k0 += 32) {
        #pragma unroll
        for (int it = 0; it < 4; it++) {
            int idx = t + it * 256;        // 0..1023
            int bb = idx >> 5, kk = idx & 31;
            int k = k0 + kk;
            Gs[bb][kk] = (k < kEnd) ? g_gate[bb * F_LEN + k] : 0.f;
        }
        #pragma unroll
        for (int it = 0; it < 8; it++) {
            int idx = t + it * 256;        // 0..2047
            int oo = idx >> 5, kk = idx & 31;
            int k = k0 + kk, o = oBase + oo;
            Ws[oo][kk] = (k < kEnd && o < F_LEN) ? W1[(size_t)o * F_LEN + k] : 0.f;
        }
        __syncthreads();
        #pragma unroll
        for (int kk = 0; kk < 32; kk++) {
            float g0 = Gs[ty][kk],      g1 = Gs[ty + 16][kk];
            float w0 = Ws[tx][kk],      w1 = Ws[tx + 16][kk];
            float w2 = Ws[tx + 32][kk], w3 = Ws[tx + 48][kk];
            acc[0][0] = fmaf(g0, w0, acc[0][0]);
            acc[0][1] = fmaf(g0, w1, acc[0][1]);
            acc[0][2] = fmaf(g0, w2, acc[0][2]);
            acc[0][3] = fmaf(g0, w3, acc[0][3]);
            acc[1][0] = fmaf(g1, w0, acc[1][0]);
            acc[1][1] = fmaf(g1, w1, acc[1][1]);
            acc[1][2] = fmaf(g1, w2, acc[1][2]);
            acc[1][3] = fmaf(g1, w3, acc[1][3]);
        }
        __syncthreads();
    }
    #pragma unroll
    for (int i = 0; i < 2; i++)
        #pragma unroll
        for (int j = 0; j < 4; j++)
            g_part[blockIdx.y][ty + 16 * i][oBase + tx + 16 * j] = acc[i][j];
}

// ---------------- kernel 2b-red: sum partials + bias + relu ----------------
__global__ void k2b_red(const float* __restrict__ b1) {
    int i = blockIdx.x * blockDim.x + threadIdx.x;
    if (i >= B_SZ * F_LEN) return;
    int b = i / F_LEN, o = i - b * F_LEN;
    float s = 0.f;
    #pragma unroll
    for (int ks = 0; ks < KSPL; ks++) s += g_part[ks][b][o];
    g_h[i] = fmaxf(s + b1[o], 0.f);
}

// ---------------- kernel 2c: logits + softmax ----------------
__global__ __launch_bounds__(256) void k2c_gate(const float* __restrict__ W2,
                                                const float* __restrict__ b2,
                                                float* __restrict__ out_scores) {
    __shared__ float red[256];
    __shared__ float logits[E_NUM];
    int b = blockIdx.x, tid = threadIdx.x;
    float acc[E_NUM];
    #pragma unroll
    for (int e = 0; e < E_NUM; e++) acc[e] = 0.f;
    for (int f = tid; f < F_LEN; f += 256) {
        float hv = g_h[b * F_LEN + f];
        #pragma unroll
        for (int e = 0; e < E_NUM; e++) acc[e] = fmaf(hv, W2[e * F_LEN + f], acc[e]);
    }
    for (int e = 0; e < E_NUM; e++) {
        red[tid] = acc[e]; __syncthreads();
        for (int o = 128; o > 0; o >>= 1) { if (tid < o) red[tid] += red[tid + o]; __syncthreads(); }
        if (tid == 0) logits[e] = red[0] + b2[e];
        __syncthreads();
    }
    if (tid == 0) {
        float mx = logits[0];
        for (int e = 1; e < E_NUM; e++) mx = fmaxf(mx, logits[e]);
        float sm = 0.f, ex[E_NUM];
        for (int e = 0; e < E_NUM; e++) { ex[e] = expf(logits[e] - mx); sm += ex[e]; }
        float is = 1.0f / sm;
        for (int e = 0; e < E_NUM; e++) {
            float v = ex[e] * is;
            g_scores[b * E_NUM + e] = v;
            out_scores[b * E_NUM + e] = v;
        }
    }
}

// ---------------- kernel 3: expert band irfft (half-length trick) ----------------
// NOTE: out_exp has an ODD float offset into d_out (tuple layout), so stores
// must be scalar 4-byte STG — float2 stores trap with misaligned address.
__global__ __launch_bounds__(NTF, 8) void k3_expert(float* __restrict__ out_exp) {
    __shared__ float2 a[M_FFT];
    __shared__ float2 tw[1024];

    int blk = blockIdx.x;                 // b*64 + e*8 + c
    int c = blk & 7;
    int e = (blk >> 3) & 7;
    int b = blk >> 6;
    int row = b * C_SZ + c;
    int tid = threadIdx.x;

    int lo = g_idx[e], hi = g_idx[e + 1];
    fill_tw(tw, tid);
    __syncthreads();

    const float2* fr = g_freq + (size_t)row * F_LEN;
    for (int k = tid; k < M_FFT; k += NTF) {
        int km = M_FFT - k;               // in [1,2048]; k=0 -> 2048 (Nyquist)
        float2 A = make_float2(0.f, 0.f), B = make_float2(0.f, 0.f);
        if (k >= lo && k < hi)  A = fr[k];
        if (km >= lo && km < hi) B = fr[km];
        float2 P  = make_float2(A.x + B.x, A.y - B.y);     // A + conj(B)
        float2 Qw = make_float2(A.x - B.x, A.y + B.y);     // A - conj(B)
        float2 w = w4096(tw, k);
        float2 cw = make_float2(w.x, -w.y);                // e^{+2pi i k/N}
        float2 Xo2 = cmul(Qw, cw);
        // Z2 = P + i*Xo2
        a[brev11(k)] = make_float2(P.x - Xo2.y, P.y + Xo2.x);
    }
    __syncthreads();

    fft2048<true>(a, tw, tid);

    float* o = out_exp + (size_t)blk * N_FFT;
    const float sc = 1.0f / (float)N_FFT;                  // (1/2)*(1/2048)
    for (int n = tid; n < M_FFT; n += NTF) {
        float2 v = a[n];
        o[2 * n]     = v.x * sc;
        o[2 * n + 1] = v.y * sc;
    }
}

// ---------------- kernel 4: gated combine irfft + denorm ----------------
__global__ __launch_bounds__(NTF, 8) void k4_combined(float* __restrict__ out_comb) {
    __shared__ float2 a[M_FFT];
    __shared__ float2 tw[1024];
    __shared__ int   s_idx[E_NUM + 1];
    __shared__ float s_g[E_NUM];

    int row = blockIdx.x;
    int b = row / C_SZ;
    int tid = threadIdx.x;

    if (tid < E_NUM + 1) s_idx[tid] = g_idx[tid];
    if (tid >= 32 && tid < 32 + E_NUM) s_g[tid - 32] = g_scores[b * E_NUM + (tid - 32)];
    fill_tw(tw, tid);
    __syncthreads();

    const float2* fr = g_freq + (size_t)row * F_LEN;
    for (int k = tid; k < M_FFT; k += NTF) {
        int km = M_FFT - k;
        int ea = 0, eb = 0;
        while (ea < E_NUM - 1 && k  >= s_idx[ea + 1]) ea++;
        while (eb < E_NUM - 1 && km >= s_idx[eb + 1]) eb++;
        float ga = s_g[ea], gb = s_g[eb];
        float2 Af = fr[k];
        float2 Bf = fr[km];
        float2 A = make_float2(Af.x * ga, Af.y * ga);
        float2 B = make_float2(Bf.x * gb, Bf.y * gb);
        float2 P  = make_float2(A.x + B.x, A.y - B.y);
        float2 Qw = make_float2(A.x - B.x, A.y + B.y);
        float2 w = w4096(tw, k);
        float2 cw = make_float2(w.x, -w.y);
        float2 Xo2 = cmul(Qw, cw);
        a[brev11(k)] = make_float2(P.x - Xo2.y, P.y + Xo2.x);
    }
    __syncthreads();

    fft2048<true>(a, tw, tid);

    float mean = g_mean[row], stdv = g_std[row];
    float2* o = (float2*)(out_comb + (size_t)row * N_FFT);   // offset 0: 8B-aligned
    const float sc = 1.0f / (float)N_FFT;
    for (int n = tid; n < M_FFT; n += NTF)
        o[n] = make_float2(fmaf(a[n].x * sc, stdv, mean),
                           fmaf(a[n].y * sc, stdv, mean));
}

// ---------------- launch ----------------
extern "C" void kernel_launch(void* const* d_in, const int* in_sizes, int n_in,
                              void* d_out, int out_size) {
    const float* x   = (const float*)d_in[0];
    const float* raw = (const float*)d_in[1];
    const float* W1  = (const float*)d_in[2];
    const float* b1  = (const float*)d_in[3];
    const float* W2  = (const float*)d_in[4];
    const float* b2  = (const float*)d_in[5];
    float* out = (float*)d_out;

    const int comb_n   = B_SZ * C_SZ * N_FFT;
    const int bounds_n = E_NUM + 1;
    const int scores_n = B_SZ * E_NUM;
    const int exp_n    = B_SZ * E_NUM * C_SZ * N_FFT;
    const int total_n  = comb_n + bounds_n + scores_n + exp_n;

    bool full = (out_size >= total_n);

    float* out_comb = out;
    float* out_bounds;
    float* out_scores;
    float* out_exp = nullptr;

    if (full) {
        out_bounds = out + comb_n;
        out_scores = out_bounds + bounds_n;
        out_exp    = out_scores + scores_n;
    } else {
        cudaGetSymbolAddress((void**)&out_bounds, g_dummy);
        out_scores = out_bounds + 16;
    }

    k1_norm_fft<<<NROW, NTF>>>(x);
    k1b_gate<<<(B_SZ * F_LEN + 255) / 256, 256>>>();
    k2a_bounds<<<1, 1>>>(raw, out_bounds);
    k2b_part<<<dim3(33, KSPL), 256>>>(W1);
    k2b_red<<<(B_SZ * F_LEN + 255) / 256, 256>>>(b1);
    k2c_gate<<<B_SZ, 256>>>(W2, b2, out_scores);
    if (full) {
        k3_expert<<<B_SZ * E_NUM * C_SZ, NTF>>>(out_exp);
    }
    k4_combined<<<NROW, NTF>>>(out_comb);
}

// round 6
// speedup vs baseline: 2.9581x; 1.4210x over previous
#include <cuda_runtime.h>

#define N_FFT  4096
#define M_FFT  2048
#define F_LEN  2049
#define B_SZ   32
#define C_SZ   8
#define E_NUM  8
#define NROW   (B_SZ * C_SZ)     // 256
#define NTF    256               // threads for FFT kernels
#define OSPAN  2112              // 33 * 64
#define KSPL   33                // K splits of 64

// ---------------- device scratch (no allocations allowed) ----------------
__device__ float2 g_freq[NROW * F_LEN];     // spectrum per (b,c)
__device__ float  g_gate[B_SZ * F_LEN];     // gating input [B, F]
__device__ float  g_mean[NROW];
__device__ float  g_std[NROW];
__device__ float  g_h[B_SZ * F_LEN];        // hidden layer
__device__ float  g_scores[B_SZ * E_NUM];
__device__ int    g_idx[E_NUM + 1];
__device__ float  g_part[KSPL][B_SZ][OSPAN];
__device__ float2 g_tw[1024];               // e^{-2*pi*i*k/4096}, k in [0,1024)
__device__ float  g_dummy[16 + B_SZ * E_NUM];

// ---------------- helpers ----------------
__device__ __forceinline__ int brev11(int i) { return (int)(__brev((unsigned)i) >> 21); }

__device__ __forceinline__ float2 cmul(float2 a, float2 b) {
    return make_float2(a.x * b.x - a.y * b.y, a.x * b.y + a.y * b.x);
}

__device__ __forceinline__ void load_tw(float2* tw, int tid) {
    #pragma unroll
    for (int k = tid; k < 1024; k += NTF) tw[k] = g_tw[k];
}

// e^{-2*pi*i*k/4096} for k in [0,2048)
__device__ __forceinline__ float2 w4096(const float2* tw, int k) {
    if (k < 1024) return tw[k];
    float2 u = tw[k - 1024];                 // * exp(-i*pi/2) = -i
    return make_float2(u.y, -u.x);
}

// ---------------- kernel 0: twiddle table ----------------
__global__ void k0_tw() {
    int k = blockIdx.x * blockDim.x + threadIdx.x;
    if (k < 1024) {
        float s, c;
        sincospif(-(float)k / 2048.0f, &s, &c);
        g_tw[k] = make_float2(c, s);
    }
}

// in-place FFT, length 2048, radix-2 schedule with pairs of stages fused into
// radix-4 passes (5 fused passes + 1 final radix-2 stage = 6 syncs).
// Input bit-reversed (brev11), output natural order.
template <bool INV>
__device__ void fft2048(float2* a, const float2* tw, int tid) {
    #pragma unroll
    for (int s = 0; s < 10; s += 2) {
        int h = 1 << s;
        #pragma unroll 2
        for (int t = tid; t < M_FFT / 4; t += NTF) {
            int j = t & (h - 1);
            int i0 = ((t >> s) << (s + 2)) + j;
            float2 w1 = w4096(tw, j << (11 - s));   // W(j, 2h)
            float2 w2 = tw[j << (10 - s)];          // W(j, 4h)
            if (INV) { w1.y = -w1.y; w2.y = -w2.y; }
            float2 x0 = a[i0], x1 = a[i0 + h], x2 = a[i0 + 2 * h], x3 = a[i0 + 3 * h];
            float2 t1 = cmul(w1, x1);
            float2 t3 = cmul(w1, x3);
            float2 y0 = make_float2(x0.x + t1.x, x0.y + t1.y);
            float2 y1 = make_float2(x0.x - t1.x, x0.y - t1.y);
            float2 y2 = make_float2(x2.x + t3.x, x2.y + t3.y);
            float2 y3 = make_float2(x2.x - t3.x, x2.y - t3.y);
            float2 u2 = cmul(w2, y2);
            float2 u3 = cmul(w2, y3);
            // forward: (-i)*u3 ; inverse: (+i)*u3
            float2 v3 = INV ? make_float2(-u3.y, u3.x) : make_float2(u3.y, -u3.x);
            a[i0]         = make_float2(y0.x + u2.x, y0.y + u2.y);
            a[i0 + 2 * h] = make_float2(y0.x - u2.x, y0.y - u2.y);
            a[i0 + h]     = make_float2(y1.x + v3.x, y1.y + v3.y);
            a[i0 + 3 * h] = make_float2(y1.x - v3.x, y1.y - v3.y);
        }
        __syncthreads();
    }
    // final radix-2 stage, s = 10 (h = 1024)
    #pragma unroll 4
    for (int t = tid; t < 1024; t += NTF) {
        float2 w = w4096(tw, t << 1);
        if (INV) w.y = -w.y;
        float2 u = a[t];
        float2 v = cmul(a[t + 1024], w);
        a[t]        = make_float2(u.x + v.x, u.y + v.y);
        a[t + 1024] = make_float2(u.x - v.x, u.y - v.y);
    }
    __syncthreads();
}

// ---------------- kernel 1: norm + forward rfft via half-length trick ----------------
__global__ __launch_bounds__(NTF, 8) void k1_norm_fft(const float* __restrict__ x) {
    __shared__ float2 a[M_FFT];       // 16 KB : packed z[n] = xn[2n] + i xn[2n+1]
    __shared__ float2 tw[1024];       // 8 KB
    __shared__ float  red[16];

    int row = blockIdx.x;
    int tid = threadIdx.x;
    int lane = tid & 31, wid = tid >> 5;

    load_tw(tw, tid);

    const float4* xr = (const float4*)(x + (size_t)row * N_FFT);
    float s = 0.f, ss = 0.f;
    for (int i = tid; i < N_FFT / 4; i += NTF) {
        float4 v = xr[i];
        a[2 * i]     = make_float2(v.x, v.y);
        a[2 * i + 1] = make_float2(v.z, v.w);
        s  += (v.x + v.y) + (v.z + v.w);
        ss += v.x * v.x + v.y * v.y + v.z * v.z + v.w * v.w;
    }
    #pragma unroll
    for (int o = 16; o; o >>= 1) {
        s  += __shfl_xor_sync(0xffffffffu, s, o);
        ss += __shfl_xor_sync(0xffffffffu, ss, o);
    }
    if (lane == 0) { red[wid] = s; red[wid + 8] = ss; }
    __syncthreads();
    float sum = 0.f, sumsq = 0.f;
    #pragma unroll
    for (int i = 0; i < 8; i++) { sum += red[i]; sumsq += red[8 + i]; }

    float mean = sum * (1.0f / N_FFT);
    float var  = (sumsq - sum * mean) * (1.0f / (N_FFT - 1)) + 1e-5f;
    float stdv = sqrtf(var);
    float inv  = 1.0f / stdv;
    if (tid == 0) { g_mean[row] = mean; g_std[row] = stdv; }
    __syncthreads();

    // normalize + bit-reversal permutation (disjoint swap pairs)
    for (int n = tid; n < M_FFT; n += NTF) {
        int r = brev11(n);
        if (r > n) {
            float2 u = a[n], v = a[r];
            a[n] = make_float2((v.x - mean) * inv, (v.y - mean) * inv);
            a[r] = make_float2((u.x - mean) * inv, (u.y - mean) * inv);
        } else if (r == n) {
            float2 u = a[n];
            a[n] = make_float2((u.x - mean) * inv, (u.y - mean) * inv);
        }
    }
    __syncthreads();

    fft2048<false>(a, tw, tid);

    // unpack: X[k] = (P - i*w*Q)/2, P = Z[k]+conj(Z[M-k]), Q = Z[k]-conj(Z[M-k])
    float2* fr = g_freq + (size_t)row * F_LEN;
    for (int k = tid; k < M_FFT; k += NTF) {
        float2 Zk = a[k];
        float2 Zm = a[(M_FFT - k) & (M_FFT - 1)];
        float2 P = make_float2(Zk.x + Zm.x, Zk.y - Zm.y);
        float2 Q = make_float2(Zk.x - Zm.x, Zk.y + Zm.y);
        float2 w = w4096(tw, k);
        float2 t = cmul(w, Q);                      // w*Q ; X = (P - i*t)/2
        fr[k] = make_float2(0.5f * (P.x + t.y), 0.5f * (P.y - t.x));
    }
    if (tid == 0) fr[M_FFT] = make_float2(a[0].x - a[0].y, 0.f);
}

// ---------------- kernel 1b: gating input = mean_c |freq| ----------------
__global__ void k1b_gate() {
    int i = blockIdx.x * blockDim.x + threadIdx.x;
    if (i >= B_SZ * F_LEN) return;
    int b = i / F_LEN;
    int f = i - b * F_LEN;
    float acc = 0.f;
    #pragma unroll
    for (int c = 0; c < C_SZ; c++) {
        float2 v = g_freq[(size_t)(b * C_SZ + c) * F_LEN + f];
        acc += sqrtf(v.x * v.x + v.y * v.y);
    }
    g_gate[i] = acc * (1.0f / C_SZ);
}

// ---------------- kernel 2a: boundaries / band edges ----------------
__global__ void k2a_bounds(const float* __restrict__ raw, float* __restrict__ out_bounds) {
    float b[E_NUM - 1];
    for (int i = 0; i < E_NUM - 1; i++) b[i] = 1.0f / (1.0f + expf(-raw[i]));
    for (int i = 1; i < E_NUM - 1; i++) {
        float v = b[i]; int j = i - 1;
        while (j >= 0 && b[j] > v) { b[j + 1] = b[j]; j--; }
        b[j + 1] = v;
    }
    float bd[E_NUM + 1];
    bd[0] = 0.f;
    for (int i = 0; i < E_NUM - 1; i++) bd[i + 1] = b[i];
    bd[E_NUM] = 1.f;
    for (int i = 0; i <= E_NUM; i++) {
        out_bounds[i] = bd[i];
        g_idx[i] = (int)floorf(bd[i] * (float)F_LEN);
    }
    g_idx[E_NUM] = F_LEN;
}

// ---------------- kernel 2b: partial GEMM h_part = G @ W1^T (K-split x33) ----------------
__global__ __launch_bounds__(256) void k2b_part(const float* __restrict__ W1) {
    __shared__ float Gs[32][33];
    __shared__ float Ws[64][33];
    int t  = threadIdx.x;
    int tx = t & 15, ty = t >> 4;
    int oBase = blockIdx.x * 64;
    int kBase = blockIdx.y * 64;
    int kEnd  = min(kBase + 64, F_LEN);

    float acc[2][4] = {};
    for (int k0 = kBase; k0 < kEnd; k0 += 32) {
        #pragma unroll
        for (int it = 0; it < 4; it++) {
            int idx = t + it * 256;        // 0..1023
            int bb = idx >> 5, kk = idx & 31;
            int k = k0 + kk;
            Gs[bb][kk] = (k < kEnd) ? g_gate[bb * F_LEN + k] : 0.f;
        }
        #pragma unroll
        for (int it = 0; it < 8; it++) {
            int idx = t + it * 256;        // 0..2047
            int oo = idx >> 5, kk = idx & 31;
            int k = k0 + kk, o = oBase + oo;
            Ws[oo][kk] = (k < kEnd && o < F_LEN) ? W1[(size_t)o * F_LEN + k] : 0.f;
        }
        __syncthreads();
        #pragma unroll
        for (int kk = 0; kk < 32; kk++) {
            float g0 = Gs[ty][kk],      g1 = Gs[ty + 16][kk];
            float w0 = Ws[tx][kk],      w1 = Ws[tx + 16][kk];
            float w2 = Ws[tx + 32][kk], w3 = Ws[tx + 48][kk];
            acc[0][0] = fmaf(g0, w0, acc[0][0]);
            acc[0][1] = fmaf(g0, w1, acc[0][1]);
            acc[0][2] = fmaf(g0, w2, acc[0][2]);
            acc[0][3] = fmaf(g0, w3, acc[0][3]);
            acc[1][0] = fmaf(g1, w0, acc[1][0]);
            acc[1][1] = fmaf(g1, w1, acc[1][1]);
            acc[1][2] = fmaf(g1, w2, acc[1][2]);
            acc[1][3] = fmaf(g1, w3, acc[1][3]);
        }
        __syncthreads();
    }
    #pragma unroll
    for (int i = 0; i < 2; i++)
        #pragma unroll
        for (int j = 0; j < 4; j++)
            g_part[blockIdx.y][ty + 16 * i][oBase + tx + 16 * j] = acc[i][j];
}

// ---------------- kernel 2b-red: sum partials + bias + relu ----------------
__global__ void k2b_red(const float* __restrict__ b1) {
    int i = blockIdx.x * blockDim.x + threadIdx.x;
    if (i >= B_SZ * F_LEN) return;
    int b = i / F_LEN, o = i - b * F_LEN;
    float s = 0.f;
    #pragma unroll
    for (int ks = 0; ks < KSPL; ks++) s += g_part[ks][b][o];
    g_h[i] = fmaxf(s + b1[o], 0.f);
}

// ---------------- kernel 2c: logits + softmax ----------------
__global__ __launch_bounds__(256) void k2c_gate(const float* __restrict__ W2,
                                                const float* __restrict__ b2,
                                                float* __restrict__ out_scores) {
    __shared__ float red[256];
    __shared__ float logits[E_NUM];
    int b = blockIdx.x, tid = threadIdx.x;
    float acc[E_NUM];
    #pragma unroll
    for (int e = 0; e < E_NUM; e++) acc[e] = 0.f;
    for (int f = tid; f < F_LEN; f += 256) {
        float hv = g_h[b * F_LEN + f];
        #pragma unroll
        for (int e = 0; e < E_NUM; e++) acc[e] = fmaf(hv, W2[e * F_LEN + f], acc[e]);
    }
    for (int e = 0; e < E_NUM; e++) {
        red[tid] = acc[e]; __syncthreads();
        for (int o = 128; o > 0; o >>= 1) { if (tid < o) red[tid] += red[tid + o]; __syncthreads(); }
        if (tid == 0) logits[e] = red[0] + b2[e];
        __syncthreads();
    }
    if (tid == 0) {
        float mx = logits[0];
        for (int e = 1; e < E_NUM; e++) mx = fmaxf(mx, logits[e]);
        float sm = 0.f, ex[E_NUM];
        for (int e = 0; e < E_NUM; e++) { ex[e] = expf(logits[e] - mx); sm += ex[e]; }
        float is = 1.0f / sm;
        for (int e = 0; e < E_NUM; e++) {
            float v = ex[e] * is;
            g_scores[b * E_NUM + e] = v;
            out_scores[b * E_NUM + e] = v;
        }
    }
}

// ---------------- kernel 3: expert band irfft (half-length trick) ----------------
// NOTE: out_exp has an ODD float offset into d_out (tuple layout), so stores
// must be scalar 4-byte STG — float2 stores trap with misaligned address.
__global__ __launch_bounds__(NTF, 8) void k3_expert(float* __restrict__ out_exp) {
    __shared__ float2 a[M_FFT];
    __shared__ float2 tw[1024];

    int blk = blockIdx.x;                 // b*64 + e*8 + c
    int c = blk & 7;
    int e = (blk >> 3) & 7;
    int b = blk >> 6;
    int row = b * C_SZ + c;
    int tid = threadIdx.x;

    int lo = g_idx[e], hi = g_idx[e + 1];
    load_tw(tw, tid);
    __syncthreads();

    const float2* fr = g_freq + (size_t)row * F_LEN;
    for (int k = tid; k < M_FFT; k += NTF) {
        int km = M_FFT - k;               // in [1,2048]; k=0 -> 2048 (Nyquist)
        float2 A = make_float2(0.f, 0.f), B = make_float2(0.f, 0.f);
        if (k >= lo && k < hi)  A = fr[k];
        if (km >= lo && km < hi) B = fr[km];
        float2 P  = make_float2(A.x + B.x, A.y - B.y);     // A + conj(B)
        float2 Qw = make_float2(A.x - B.x, A.y + B.y);     // A - conj(B)
        float2 w = w4096(tw, k);
        float2 cw = make_float2(w.x, -w.y);                // e^{+2pi i k/N}
        float2 Xo2 = cmul(Qw, cw);
        // Z2 = P + i*Xo2
        a[brev11(k)] = make_float2(P.x - Xo2.y, P.y + Xo2.x);
    }
    __syncthreads();

    fft2048<true>(a, tw, tid);

    float* o = out_exp + (size_t)blk * N_FFT;
    const float sc = 1.0f / (float)N_FFT;                  // (1/2)*(1/2048)
    for (int n = tid; n < M_FFT; n += NTF) {
        float2 v = a[n];
        o[2 * n]     = v.x * sc;
        o[2 * n + 1] = v.y * sc;
    }
}

// ---------------- kernel 4: gated combine irfft + denorm ----------------
__global__ __launch_bounds__(NTF, 8) void k4_combined(float* __restrict__ out_comb) {
    __shared__ float2 a[M_FFT];
    __shared__ float2 tw[1024];
    __shared__ int   s_idx[E_NUM + 1];
    __shared__ float s_g[E_NUM];

    int row = blockIdx.x;
    int b = row / C_SZ;
    int tid = threadIdx.x;

    if (tid < E_NUM + 1) s_idx[tid] = g_idx[tid];
    if (tid >= 32 && tid < 32 + E_NUM) s_g[tid - 32] = g_scores[b * E_NUM + (tid - 32)];
    load_tw(tw, tid);
    __syncthreads();

    const float2* fr = g_freq + (size_t)row * F_LEN;
    for (int k = tid; k < M_FFT; k += NTF) {
        int km = M_FFT - k;
        int ea = 0, eb = 0;
        while (ea < E_NUM - 1 && k  >= s_idx[ea + 1]) ea++;
        while (eb < E_NUM - 1 && km >= s_idx[eb + 1]) eb++;
        float ga = s_g[ea], gb = s_g[eb];
        float2 Af = fr[k];
        float2 Bf = fr[km];
        float2 A = make_float2(Af.x * ga, Af.y * ga);
        float2 B = make_float2(Bf.x * gb, Bf.y * gb);
        float2 P  = make_float2(A.x + B.x, A.y - B.y);
        float2 Qw = make_float2(A.x - B.x, A.y + B.y);
        float2 w = w4096(tw, k);
        float2 cw = make_float2(w.x, -w.y);
        float2 Xo2 = cmul(Qw, cw);
        a[brev11(k)] = make_float2(P.x - Xo2.y, P.y + Xo2.x);
    }
    __syncthreads();

    fft2048<true>(a, tw, tid);

    float mean = g_mean[row], stdv = g_std[row];
    float2* o = (float2*)(out_comb + (size_t)row * N_FFT);   // offset 0: 8B-aligned
    const float sc = 1.0f / (float)N_FFT;
    for (int n = tid; n < M_FFT; n += NTF)
        o[n] = make_float2(fmaf(a[n].x * sc, stdv, mean),
                           fmaf(a[n].y * sc, stdv, mean));
}

// ---------------- launch ----------------
extern "C" void kernel_launch(void* const* d_in, const int* in_sizes, int n_in,
                              void* d_out, int out_size) {
    const float* x   = (const float*)d_in[0];
    const float* raw = (const float*)d_in[1];
    const float* W1  = (const float*)d_in[2];
    const float* b1  = (const float*)d_in[3];
    const float* W2  = (const float*)d_in[4];
    const float* b2  = (const float*)d_in[5];
    float* out = (float*)d_out;

    const int comb_n   = B_SZ * C_SZ * N_FFT;
    const int bounds_n = E_NUM + 1;
    const int scores_n = B_SZ * E_NUM;
    const int exp_n    = B_SZ * E_NUM * C_SZ * N_FFT;
    const int total_n  = comb_n + bounds_n + scores_n + exp_n;

    bool full = (out_size >= total_n);

    float* out_comb = out;
    float* out_bounds;
    float* out_scores;
    float* out_exp = nullptr;

    if (full) {
        out_bounds = out + comb_n;
        out_scores = out_bounds + bounds_n;
        out_exp    = out_scores + scores_n;
    } else {
        cudaGetSymbolAddress((void**)&out_bounds, g_dummy);
        out_scores = out_bounds + 16;
    }

    k0_tw<<<4, 256>>>();
    k1_norm_fft<<<NROW, NTF>>>(x);
    k1b_gate<<<(B_SZ * F_LEN + 255) / 256, 256>>>();
    k2a_bounds<<<1, 1>>>(raw, out_bounds);
    k2b_part<<<dim3(33, KSPL), 256>>>(W1);
    k2b_red<<<(B_SZ * F_LEN + 255) / 256, 256>>>(b1);
    k2c_gate<<<B_SZ, 256>>>(W2, b2, out_scores);
    if (full) {
        k3_expert<<<B_SZ * E_NUM * C_SZ, NTF>>>(out_exp);
    }
    k4_combined<<<NROW, NTF>>>(out_comb);
}

// round 7
// speedup vs baseline: 3.1393x; 1.0613x over previous
#include <cuda_runtime.h>

#define N_FFT  4096
#define M_FFT  2048
#define F_LEN  2049
#define B_SZ   32
#define C_SZ   8
#define E_NUM  8
#define NROW   (B_SZ * C_SZ)     // 256
#define NTF    256               // threads for FFT kernels
#define OSPAN  2112              // 33 * 64
#define KSPL   33                // K splits of 64

// ---------------- device scratch (no allocations allowed) ----------------
__device__ float2 g_freq[NROW * F_LEN];     // spectrum per (b,c)
__device__ float  g_gate[B_SZ * F_LEN];     // gating input [B, F]
__device__ float  g_mean[NROW];
__device__ float  g_std[NROW];
__device__ float  g_h[B_SZ * F_LEN];        // hidden layer
__device__ float  g_scores[B_SZ * E_NUM];
__device__ int    g_idx[E_NUM + 1];
__device__ float  g_part[KSPL][B_SZ][OSPAN];
__device__ float2 g_tw[1024];               // e^{-2*pi*i*k/4096}, k in [0,1024)
__device__ float  g_dummy[16 + B_SZ * E_NUM];

// ---------------- helpers ----------------
__device__ __forceinline__ int brev11(int i) { return (int)(__brev((unsigned)i) >> 21); }

__device__ __forceinline__ float2 cmul(float2 a, float2 b) {
    return make_float2(a.x * b.x - a.y * b.y, a.x * b.y + a.y * b.x);
}

__device__ __forceinline__ void load_tw(float2* tw, int tid) {
    #pragma unroll
    for (int k = tid; k < 1024; k += NTF) tw[k] = g_tw[k];
}

// e^{-2*pi*i*k/4096}, k in [0,2048) — from smem table
__device__ __forceinline__ float2 w4096(const float2* tw, int k) {
    if (k < 1024) return tw[k];
    float2 u = tw[k - 1024];                 // * exp(-i*pi/2) = -i
    return make_float2(u.y, -u.x);
}

// same from global table (used in fused gather, L1-resident)
__device__ __forceinline__ float2 w4096g(int k) {
    if (k < 1024) return g_tw[k];
    float2 u = g_tw[k - 1024];
    return make_float2(u.y, -u.x);
}

// ---------------- kernel 0: twiddle table + boundaries ----------------
__global__ void k0_init(const float* __restrict__ raw, float* __restrict__ out_bounds) {
    int k = blockIdx.x * blockDim.x + threadIdx.x;
    if (k < 1024) {
        float s, c;
        sincospif(-(float)k / 2048.0f, &s, &c);
        g_tw[k] = make_float2(c, s);
    }
    if (k == 0) {
        float b[E_NUM - 1];
        for (int i = 0; i < E_NUM - 1; i++) b[i] = 1.0f / (1.0f + expf(-raw[i]));
        for (int i = 1; i < E_NUM - 1; i++) {
            float v = b[i]; int j = i - 1;
            while (j >= 0 && b[j] > v) { b[j + 1] = b[j]; j--; }
            b[j + 1] = v;
        }
        float bd[E_NUM + 1];
        bd[0] = 0.f;
        for (int i = 0; i < E_NUM - 1; i++) bd[i + 1] = b[i];
        bd[E_NUM] = 1.f;
        for (int i = 0; i <= E_NUM; i++) {
            out_bounds[i] = bd[i];
            g_idx[i] = (int)floorf(bd[i] * (float)F_LEN);
        }
        g_idx[E_NUM] = F_LEN;
    }
}

// full FFT, length 2048 (used by k1 forward): 5 radix-4 passes + final radix-2.
// Input bit-reversed (brev11) in smem, output natural order.
template <bool INV>
__device__ void fft2048(float2* a, const float2* tw, int tid) {
    #pragma unroll
    for (int s = 0; s < 10; s += 2) {
        int h = 1 << s;
        #pragma unroll 2
        for (int t = tid; t < M_FFT / 4; t += NTF) {
            int j = t & (h - 1);
            int i0 = ((t >> s) << (s + 2)) + j;
            float2 w1 = w4096(tw, j << (11 - s));
            float2 w2 = tw[j << (10 - s)];
            if (INV) { w1.y = -w1.y; w2.y = -w2.y; }
            float2 x0 = a[i0], x1 = a[i0 + h], x2 = a[i0 + 2 * h], x3 = a[i0 + 3 * h];
            float2 t1 = cmul(w1, x1);
            float2 t3 = cmul(w1, x3);
            float2 y0 = make_float2(x0.x + t1.x, x0.y + t1.y);
            float2 y1 = make_float2(x0.x - t1.x, x0.y - t1.y);
            float2 y2 = make_float2(x2.x + t3.x, x2.y + t3.y);
            float2 y3 = make_float2(x2.x - t3.x, x2.y - t3.y);
            float2 u2 = cmul(w2, y2);
            float2 u3 = cmul(w2, y3);
            float2 v3 = INV ? make_float2(-u3.y, u3.x) : make_float2(u3.y, -u3.x);
            a[i0]         = make_float2(y0.x + u2.x, y0.y + u2.y);
            a[i0 + 2 * h] = make_float2(y0.x - u2.x, y0.y - u2.y);
            a[i0 + h]     = make_float2(y1.x + v3.x, y1.y + v3.y);
            a[i0 + 3 * h] = make_float2(y1.x - v3.x, y1.y - v3.y);
        }
        __syncthreads();
    }
    #pragma unroll 4
    for (int t = tid; t < 1024; t += NTF) {
        float2 w = w4096(tw, t << 1);
        if (INV) w.y = -w.y;
        float2 u = a[t];
        float2 v = cmul(a[t + 1024], w);
        a[t]        = make_float2(u.x + v.x, u.y + v.y);
        a[t + 1024] = make_float2(u.x - v.x, u.y - v.y);
    }
    __syncthreads();
}

// middle radix-4 passes only (s = 2,4,6,8) for the fused inverse kernels
__device__ __forceinline__ void fft_mid_inv(float2* a, const float2* tw, int tid) {
    #pragma unroll
    for (int s = 2; s < 10; s += 2) {
        int h = 1 << s;
        #pragma unroll 2
        for (int t = tid; t < M_FFT / 4; t += NTF) {
            int j = t & (h - 1);
            int i0 = ((t >> s) << (s + 2)) + j;
            float2 w1 = w4096(tw, j << (11 - s));  w1.y = -w1.y;
            float2 w2 = tw[j << (10 - s)];         w2.y = -w2.y;
            float2 x0 = a[i0], x1 = a[i0 + h], x2 = a[i0 + 2 * h], x3 = a[i0 + 3 * h];
            float2 t1 = cmul(w1, x1);
            float2 t3 = cmul(w1, x3);
            float2 y0 = make_float2(x0.x + t1.x, x0.y + t1.y);
            float2 y1 = make_float2(x0.x - t1.x, x0.y - t1.y);
            float2 y2 = make_float2(x2.x + t3.x, x2.y + t3.y);
            float2 y3 = make_float2(x2.x - t3.x, x2.y - t3.y);
            float2 u2 = cmul(w2, y2);
            float2 u3 = cmul(w2, y3);
            float2 v3 = make_float2(-u3.y, u3.x);   // (+i)*u3 (inverse)
            a[i0]         = make_float2(y0.x + u2.x, y0.y + u2.y);
            a[i0 + 2 * h] = make_float2(y0.x - u2.x, y0.y - u2.y);
            a[i0 + h]     = make_float2(y1.x + v3.x, y1.y + v3.y);
            a[i0 + 3 * h] = make_float2(y1.x - v3.x, y1.y - v3.y);
        }
        __syncthreads();
    }
}

// ---------------- kernel 1: norm + forward rfft via half-length trick ----------------
__global__ __launch_bounds__(NTF, 8) void k1_norm_fft(const float* __restrict__ x) {
    __shared__ float2 a[M_FFT];       // 16 KB
    __shared__ float2 tw[1024];       // 8 KB
    __shared__ float  red[16];

    int row = blockIdx.x;
    int tid = threadIdx.x;
    int lane = tid & 31, wid = tid >> 5;

    load_tw(tw, tid);

    const float4* xr = (const float4*)(x + (size_t)row * N_FFT);
    float s = 0.f, ss = 0.f;
    for (int i = tid; i < N_FFT / 4; i += NTF) {
        float4 v = xr[i];
        a[2 * i]     = make_float2(v.x, v.y);
        a[2 * i + 1] = make_float2(v.z, v.w);
        s  += (v.x + v.y) + (v.z + v.w);
        ss += v.x * v.x + v.y * v.y + v.z * v.z + v.w * v.w;
    }
    #pragma unroll
    for (int o = 16; o; o >>= 1) {
        s  += __shfl_xor_sync(0xffffffffu, s, o);
        ss += __shfl_xor_sync(0xffffffffu, ss, o);
    }
    if (lane == 0) { red[wid] = s; red[wid + 8] = ss; }
    __syncthreads();
    float sum = 0.f, sumsq = 0.f;
    #pragma unroll
    for (int i = 0; i < 8; i++) { sum += red[i]; sumsq += red[8 + i]; }

    float mean = sum * (1.0f / N_FFT);
    float var  = (sumsq - sum * mean) * (1.0f / (N_FFT - 1)) + 1e-5f;
    float stdv = sqrtf(var);
    float inv  = 1.0f / stdv;
    if (tid == 0) { g_mean[row] = mean; g_std[row] = stdv; }
    __syncthreads();

    for (int n = tid; n < M_FFT; n += NTF) {
        int r = brev11(n);
        if (r > n) {
            float2 u = a[n], v = a[r];
            a[n] = make_float2((v.x - mean) * inv, (v.y - mean) * inv);
            a[r] = make_float2((u.x - mean) * inv, (u.y - mean) * inv);
        } else if (r == n) {
            float2 u = a[n];
            a[n] = make_float2((u.x - mean) * inv, (u.y - mean) * inv);
        }
    }
    __syncthreads();

    fft2048<false>(a, tw, tid);

    float2* fr = g_freq + (size_t)row * F_LEN;
    for (int k = tid; k < M_FFT; k += NTF) {
        float2 Zk = a[k];
        float2 Zm = a[(M_FFT - k) & (M_FFT - 1)];
        float2 P = make_float2(Zk.x + Zm.x, Zk.y - Zm.y);
        float2 Q = make_float2(Zk.x - Zm.x, Zk.y + Zm.y);
        float2 w = w4096(tw, k);
        float2 t = cmul(w, Q);
        fr[k] = make_float2(0.5f * (P.x + t.y), 0.5f * (P.y - t.x));
    }
    if (tid == 0) fr[M_FFT] = make_float2(a[0].x - a[0].y, 0.f);
}

// ---------------- kernel 1b: gating input = mean_c |freq| ----------------
__global__ void k1b_gate() {
    int i = blockIdx.x * blockDim.x + threadIdx.x;
    if (i >= B_SZ * F_LEN) return;
    int b = i / F_LEN;
    int f = i - b * F_LEN;
    float acc = 0.f;
    #pragma unroll
    for (int c = 0; c < C_SZ; c++) {
        float2 v = g_freq[(size_t)(b * C_SZ + c) * F_LEN + f];
        acc += sqrtf(v.x * v.x + v.y * v.y);
    }
    g_gate[i] = acc * (1.0f / C_SZ);
}

// ---------------- kernel 2b: partial GEMM h_part = G @ W1^T (K-split x33) ----------------
__global__ __launch_bounds__(256) void k2b_part(const float* __restrict__ W1) {
    __shared__ float Gs[32][33];
    __shared__ float Ws[64][33];
    int t  = threadIdx.x;
    int tx = t & 15, ty = t >> 4;
    int oBase = blockIdx.x * 64;
    int kBase = blockIdx.y * 64;
    int kEnd  = min(kBase + 64, F_LEN);

    float acc[2][4] = {};
    for (int k0 = kBase; k0 < kEnd; k0 += 32) {
        #pragma unroll
        for (int it = 0; it < 4; it++) {
            int idx = t + it * 256;
            int bb = idx >> 5, kk = idx & 31;
            int k = k0 + kk;
            Gs[bb][kk] = (k < kEnd) ? g_gate[bb * F_LEN + k] : 0.f;
        }
        #pragma unroll
        for (int it = 0; it < 8; it++) {
            int idx = t + it * 256;
            int oo = idx >> 5, kk = idx & 31;
            int k = k0 + kk, o = oBase + oo;
            Ws[oo][kk] = (k < kEnd && o < F_LEN) ? W1[(size_t)o * F_LEN + k] : 0.f;
        }
        __syncthreads();
        #pragma unroll
        for (int kk = 0; kk < 32; kk++) {
            float g0 = Gs[ty][kk],      g1 = Gs[ty + 16][kk];
            float w0 = Ws[tx][kk],      w1 = Ws[tx + 16][kk];
            float w2 = Ws[tx + 32][kk], w3 = Ws[tx + 48][kk];
            acc[0][0] = fmaf(g0, w0, acc[0][0]);
            acc[0][1] = fmaf(g0, w1, acc[0][1]);
            acc[0][2] = fmaf(g0, w2, acc[0][2]);
            acc[0][3] = fmaf(g0, w3, acc[0][3]);
            acc[1][0] = fmaf(g1, w0, acc[1][0]);
            acc[1][1] = fmaf(g1, w1, acc[1][1]);
            acc[1][2] = fmaf(g1, w2, acc[1][2]);
            acc[1][3] = fmaf(g1, w3, acc[1][3]);
        }
        __syncthreads();
    }
    #pragma unroll
    for (int i = 0; i < 2; i++)
        #pragma unroll
        for (int j = 0; j < 4; j++)
            g_part[blockIdx.y][ty + 16 * i][oBase + tx + 16 * j] = acc[i][j];
}

// ---------------- kernel 2b-red: sum partials + bias + relu ----------------
__global__ void k2b_red(const float* __restrict__ b1) {
    int i = blockIdx.x * blockDim.x + threadIdx.x;
    if (i >= B_SZ * F_LEN) return;
    int b = i / F_LEN, o = i - b * F_LEN;
    float s = 0.f;
    #pragma unroll
    for (int ks = 0; ks < KSPL; ks++) s += g_part[ks][b][o];
    g_h[i] = fmaxf(s + b1[o], 0.f);
}

// ---------------- kernel 2c: logits + softmax ----------------
__global__ __launch_bounds__(256) void k2c_gate(const float* __restrict__ W2,
                                                const float* __restrict__ b2,
                                                float* __restrict__ out_scores) {
    __shared__ float red[256];
    __shared__ float logits[E_NUM];
    int b = blockIdx.x, tid = threadIdx.x;
    float acc[E_NUM];
    #pragma unroll
    for (int e = 0; e < E_NUM; e++) acc[e] = 0.f;
    for (int f = tid; f < F_LEN; f += 256) {
        float hv = g_h[b * F_LEN + f];
        #pragma unroll
        for (int e = 0; e < E_NUM; e++) acc[e] = fmaf(hv, W2[e * F_LEN + f], acc[e]);
    }
    for (int e = 0; e < E_NUM; e++) {
        red[tid] = acc[e]; __syncthreads();
        for (int o = 128; o > 0; o >>= 1) { if (tid < o) red[tid] += red[tid + o]; __syncthreads(); }
        if (tid == 0) logits[e] = red[0] + b2[e];
        __syncthreads();
    }
    if (tid == 0) {
        float mx = logits[0];
        for (int e = 1; e < E_NUM; e++) mx = fmaxf(mx, logits[e]);
        float sm = 0.f, ex[E_NUM];
        for (int e = 0; e < E_NUM; e++) { ex[e] = expf(logits[e] - mx); sm += ex[e]; }
        float is = 1.0f / sm;
        for (int e = 0; e < E_NUM; e++) {
            float v = ex[e] * is;
            g_scores[b * E_NUM + e] = v;
            out_scores[b * E_NUM + e] = v;
        }
    }
}

// spectrum prep for the inverse half-length FFT: Z2(k) = P + i*(Qw * conj(w))
// where A = masked fr[k], B = masked fr[2048-k].
__device__ __forceinline__ float2 prep_band(const float2* __restrict__ fr,
                                            int k, int lo, int hi) {
    int km = M_FFT - k;                  // k=0 -> 2048 (Nyquist)
    float2 A = make_float2(0.f, 0.f), B = make_float2(0.f, 0.f);
    if (k >= lo && k < hi)   A = fr[k];
    if (km >= lo && km < hi) B = fr[km];
    float2 P  = make_float2(A.x + B.x, A.y - B.y);
    float2 Qw = make_float2(A.x - B.x, A.y + B.y);
    float2 w = w4096g(k);
    float2 cw = make_float2(w.x, -w.y);
    float2 Xo2 = cmul(Qw, cw);
    return make_float2(P.x - Xo2.y, P.y + Xo2.x);
}

// ---------------- kernel 3: expert band irfft (fully fused) ----------------
// out_exp has an ODD float offset -> scalar stores only.
__global__ __launch_bounds__(NTF, 8) void k3_expert(float* __restrict__ out_exp) {
    __shared__ float2 a[M_FFT];
    __shared__ float2 tw[1024];

    int blk = blockIdx.x;                 // b*64 + e*8 + c
    int c = blk & 7;
    int e = (blk >> 3) & 7;
    int b = blk >> 6;
    int row = b * C_SZ + c;
    int tid = threadIdx.x;

    int lo = g_idx[e], hi = g_idx[e + 1];
    load_tw(tw, tid);

    const float2* fr = g_freq + (size_t)row * F_LEN;

    // fused gather + first radix-4 pass (s=0: all twiddles are 1)
    #pragma unroll 2
    for (int t = tid; t < 512; t += NTF) {
        int base = (int)(__brev((unsigned)t) >> 23);       // brev9
        float2 x0 = prep_band(fr, base,        lo, hi);
        float2 x1 = prep_band(fr, base + 1024, lo, hi);
        float2 x2 = prep_band(fr, base + 512,  lo, hi);
        float2 x3 = prep_band(fr, base + 1536, lo, hi);
        float2 y0 = make_float2(x0.x + x1.x, x0.y + x1.y);
        float2 y1 = make_float2(x0.x - x1.x, x0.y - x1.y);
        float2 y2 = make_float2(x2.x + x3.x, x2.y + x3.y);
        float2 y3 = make_float2(x2.x - x3.x, x2.y - x3.y);
        float2 v3 = make_float2(-y3.y, y3.x);              // (+i)*y3 (inverse)
        a[4 * t]     = make_float2(y0.x + y2.x, y0.y + y2.y);
        a[4 * t + 1] = make_float2(y1.x + v3.x, y1.y + v3.y);
        a[4 * t + 2] = make_float2(y0.x - y2.x, y0.y - y2.y);
        a[4 * t + 3] = make_float2(y1.x - v3.x, y1.y - v3.y);
    }
    __syncthreads();

    fft_mid_inv(a, tw, tid);

    // fused final radix-2 stage + scaled scalar store
    float* o = out_exp + (size_t)blk * N_FFT;
    const float sc = 1.0f / (float)N_FFT;
    #pragma unroll 4
    for (int t = tid; t < 1024; t += NTF) {
        float2 w = w4096(tw, t << 1);  w.y = -w.y;
        float2 u = a[t];
        float2 v = cmul(a[t + 1024], w);
        o[2 * t]                 = (u.x + v.x) * sc;
        o[2 * t + 1]             = (u.y + v.y) * sc;
        o[2 * (t + 1024)]        = (u.x - v.x) * sc;
        o[2 * (t + 1024) + 1]    = (u.y - v.y) * sc;
    }
}

// ---------------- kernel 4: gated combine irfft + denorm (fully fused) ----------------
__device__ __forceinline__ float2 prep_gated(const float2* __restrict__ fr,
                                             int k, const int* s_idx, const float* s_g) {
    int km = M_FFT - k;
    int ea = 0, eb = 0;
    while (ea < E_NUM - 1 && k  >= s_idx[ea + 1]) ea++;
    while (eb < E_NUM - 1 && km >= s_idx[eb + 1]) eb++;
    float ga = s_g[ea], gb = s_g[eb];
    float2 Af = fr[k];
    float2 Bf = fr[km];
    float2 A = make_float2(Af.x * ga, Af.y * ga);
    float2 B = make_float2(Bf.x * gb, Bf.y * gb);
    float2 P  = make_float2(A.x + B.x, A.y - B.y);
    float2 Qw = make_float2(A.x - B.x, A.y + B.y);
    float2 w = w4096g(k);
    float2 cw = make_float2(w.x, -w.y);
    float2 Xo2 = cmul(Qw, cw);
    return make_float2(P.x - Xo2.y, P.y + Xo2.x);
}

__global__ __launch_bounds__(NTF, 8) void k4_combined(float* __restrict__ out_comb) {
    __shared__ float2 a[M_FFT];
    __shared__ float2 tw[1024];
    __shared__ int   s_idx[E_NUM + 1];
    __shared__ float s_g[E_NUM];

    int row = blockIdx.x;
    int b = row / C_SZ;
    int tid = threadIdx.x;

    if (tid < E_NUM + 1) s_idx[tid] = g_idx[tid];
    if (tid >= 32 && tid < 32 + E_NUM) s_g[tid - 32] = g_scores[b * E_NUM + (tid - 32)];
    load_tw(tw, tid);
    __syncthreads();                       // s_idx/s_g needed by gather below

    const float2* fr = g_freq + (size_t)row * F_LEN;

    #pragma unroll 2
    for (int t = tid; t < 512; t += NTF) {
        int base = (int)(__brev((unsigned)t) >> 23);
        float2 x0 = prep_gated(fr, base,        s_idx, s_g);
        float2 x1 = prep_gated(fr, base + 1024, s_idx, s_g);
        float2 x2 = prep_gated(fr, base + 512,  s_idx, s_g);
        float2 x3 = prep_gated(fr, base + 1536, s_idx, s_g);
        float2 y0 = make_float2(x0.x + x1.x, x0.y + x1.y);
        float2 y1 = make_float2(x0.x - x1.x, x0.y - x1.y);
        float2 y2 = make_float2(x2.x + x3.x, x2.y + x3.y);
        float2 y3 = make_float2(x2.x - x3.x, x2.y - x3.y);
        float2 v3 = make_float2(-y3.y, y3.x);
        a[4 * t]     = make_float2(y0.x + y2.x, y0.y + y2.y);
        a[4 * t + 1] = make_float2(y1.x + v3.x, y1.y + v3.y);
        a[4 * t + 2] = make_float2(y0.x - y2.x, y0.y - y2.y);
        a[4 * t + 3] = make_float2(y1.x - v3.x, y1.y - v3.y);
    }
    __syncthreads();

    fft_mid_inv(a, tw, tid);

    float mean = g_mean[row], stdv = g_std[row];
    float2* o = (float2*)(out_comb + (size_t)row * N_FFT);   // 8B-aligned
    const float sc = 1.0f / (float)N_FFT;
    #pragma unroll 4
    for (int t = tid; t < 1024; t += NTF) {
        float2 w = w4096(tw, t << 1);  w.y = -w.y;
        float2 u = a[t];
        float2 v = cmul(a[t + 1024], w);
        o[t]        = make_float2(fmaf((u.x + v.x) * sc, stdv, mean),
                                  fmaf((u.y + v.y) * sc, stdv, mean));
        o[t + 1024] = make_float2(fmaf((u.x - v.x) * sc, stdv, mean),
                                  fmaf((u.y - v.y) * sc, stdv, mean));
    }
}

// ---------------- launch ----------------
extern "C" void kernel_launch(void* const* d_in, const int* in_sizes, int n_in,
                              void* d_out, int out_size) {
    const float* x   = (const float*)d_in[0];
    const float* raw = (const float*)d_in[1];
    const float* W1  = (const float*)d_in[2];
    const float* b1  = (const float*)d_in[3];
    const float* W2  = (const float*)d_in[4];
    const float* b2  = (const float*)d_in[5];
    float* out = (float*)d_out;

    const int comb_n   = B_SZ * C_SZ * N_FFT;
    const int bounds_n = E_NUM + 1;
    const int scores_n = B_SZ * E_NUM;
    const int exp_n    = B_SZ * E_NUM * C_SZ * N_FFT;
    const int total_n  = comb_n + bounds_n + scores_n + exp_n;

    bool full = (out_size >= total_n);

    float* out_comb = out;
    float* out_bounds;
    float* out_scores;
    float* out_exp = nullptr;

    if (full) {
        out_bounds = out + comb_n;
        out_scores = out_bounds + bounds_n;
        out_exp    = out_scores + scores_n;
    } else {
        cudaGetSymbolAddress((void**)&out_bounds, g_dummy);
        out_scores = out_bounds + 16;
    }

    k0_init<<<4, 256>>>(raw, out_bounds);
    k1_norm_fft<<<NROW, NTF>>>(x);
    k1b_gate<<<(B_SZ * F_LEN + 255) / 256, 256>>>();
    k2b_part<<<dim3(33, KSPL), 256>>>(W1);
    k2b_red<<<(B_SZ * F_LEN + 255) / 256, 256>>>(b1);
    k2c_gate<<<B_SZ, 256>>>(W2, b2, out_scores);
    if (full) {
        k3_expert<<<B_SZ * E_NUM * C_SZ, NTF>>>(out_exp);
    }
    k4_combined<<<NROW, NTF>>>(out_comb);
}

// round 9
// speedup vs baseline: 4.0387x; 1.2865x over previous
#include <cuda_runtime.h>

#define N_FFT  4096
#define M_FFT  2048
#define F_LEN  2049
#define B_SZ   32
#define C_SZ   8
#define E_NUM  8
#define NROW   (B_SZ * C_SZ)     // 256
#define NTF    256               // threads for FFT kernels (1 radix-8 group each)
#define OTILE  128
#define OBLK   17                // ceil(2049/128)
#define OSPAN  (OBLK * OTILE)    // 2176
#define KSPL   33                // k chunks of 64

// ---------------- device scratch (no allocations allowed) ----------------
__device__ float2 g_freq[NROW * F_LEN];
__device__ float  g_gate[B_SZ * F_LEN];
__device__ float  g_mean[NROW];
__device__ float  g_std[NROW];
__device__ float  g_h[B_SZ * F_LEN];
__device__ float  g_scores[B_SZ * E_NUM];
__device__ int    g_idx[E_NUM + 1];
__device__ float  g_part[KSPL][B_SZ][OSPAN];
__device__ float2 g_tw[1024];               // e^{-2*pi*i*k/4096}, k in [0,1024)
__device__ float  g_dummy[16 + B_SZ * E_NUM];

#define RT2H 0.70710678118654752440f

// ---------------- helpers ----------------
__device__ __forceinline__ int brev11(int i) { return (int)(__brev((unsigned)i) >> 21); }

__device__ __forceinline__ float2 cmul(float2 a, float2 b) {
    return make_float2(a.x * b.x - a.y * b.y, a.x * b.y + a.y * b.x);
}

__device__ __forceinline__ void bf(float2& u, float2& v, float2 w) {
    float2 t = cmul(w, v);
    v = make_float2(u.x - t.x, u.y - t.y);
    u = make_float2(u.x + t.x, u.y + t.y);
}
__device__ __forceinline__ void bf1(float2& u, float2& v) {   // w = 1
    float2 t = v;
    v = make_float2(u.x - t.x, u.y - t.y);
    u = make_float2(u.x + t.x, u.y + t.y);
}

__device__ __forceinline__ void load_tw(float2* tw, int tid) {
    #pragma unroll
    for (int k = tid; k < 1024; k += NTF) tw[k] = g_tw[k];
}

// e^{-2*pi*i*k/4096}, k in [0,2048) — smem table
__device__ __forceinline__ float2 w4096(const float2* tw, int k) {
    if (k < 1024) return tw[k];
    float2 u = tw[k - 1024];
    return make_float2(u.y, -u.x);
}
// same from global (L1/L2-resident)
__device__ __forceinline__ float2 w4096g(int k) {
    if (k < 1024) return g_tw[k];
    float2 u = g_tw[k - 1024];
    return make_float2(u.y, -u.x);
}

// ---------------- radix-8 DIT pass covering stages S, S+1, S+2 ----------------
// 256 threads, one 8-point group each. In-place on smem a[2048].
template <int S, bool INV>
__device__ __forceinline__ void radix8_pass(float2* a, const float2* tw, int u) {
    const int h = 1 << S;
    int j  = u & (h - 1);
    int i0 = ((u >> S) << (S + 3)) + j;

    float2 p0 = a[i0];
    float2 p1 = a[i0 + h];
    float2 p2 = a[i0 + 2 * h];
    float2 p3 = a[i0 + 3 * h];
    float2 p4 = a[i0 + 4 * h];
    float2 p5 = a[i0 + 5 * h];
    float2 p6 = a[i0 + 6 * h];
    float2 p7 = a[i0 + 7 * h];

    float2 wa = w4096(tw, j << (11 - S));
    float2 wb = tw[j << (10 - S)];
    float2 wc = tw[j << (9 - S)];
    if (INV) { wa.y = -wa.y; wb.y = -wb.y; wc.y = -wc.y; }

    // stage S (radix-2, twiddle wa)
    bf(p0, p1, wa); bf(p2, p3, wa); bf(p4, p5, wa); bf(p6, p7, wa);
    // stage S+1: wb for even pairs, (∓i)*wb for odd pairs
    float2 wb1 = INV ? make_float2(-wb.y, wb.x) : make_float2(wb.y, -wb.x);
    bf(p0, p2, wb); bf(p1, p3, wb1); bf(p4, p6, wb); bf(p5, p7, wb1);
    // stage S+2: wc * {1, C1, ∓i, C3}
    const float2 C1 = INV ? make_float2(RT2H,  RT2H) : make_float2(RT2H, -RT2H);
    const float2 C3 = INV ? make_float2(-RT2H, RT2H) : make_float2(-RT2H, -RT2H);
    float2 wc1 = cmul(wc, C1);
    float2 wc2 = INV ? make_float2(-wc.y, wc.x) : make_float2(wc.y, -wc.x);
    float2 wc3 = cmul(wc, C3);
    bf(p0, p4, wc); bf(p1, p5, wc1); bf(p2, p6, wc2); bf(p3, p7, wc3);

    a[i0]         = p0;
    a[i0 + h]     = p1;
    a[i0 + 2 * h] = p2;
    a[i0 + 3 * h] = p3;
    a[i0 + 4 * h] = p4;
    a[i0 + 5 * h] = p5;
    a[i0 + 6 * h] = p6;
    a[i0 + 7 * h] = p7;
}

// final radix-4 (stages 9,10) in-place to smem (used by k1)
template <bool INV>
__device__ __forceinline__ void radix4_final_smem(float2* a, const float2* tw, int tid) {
    #pragma unroll
    for (int j = tid; j < 512; j += NTF) {
        float2 p0 = a[j], p1 = a[j + 512], p2 = a[j + 1024], p3 = a[j + 1536];
        float2 w1 = w4096(tw, j << 2);
        float2 w2 = w4096(tw, j << 1);
        if (INV) { w1.y = -w1.y; w2.y = -w2.y; }
        bf(p0, p1, w1); bf(p2, p3, w1);
        float2 w2b = INV ? make_float2(-w2.y, w2.x) : make_float2(w2.y, -w2.x);
        bf(p0, p2, w2); bf(p1, p3, w2b);
        a[j] = p0; a[j + 512] = p1; a[j + 1024] = p2; a[j + 1536] = p3;
    }
}

// ---------------- kernel 0: twiddle table + boundaries ----------------
__global__ void k0_init(const float* __restrict__ raw, float* __restrict__ out_bounds) {
    int k = blockIdx.x * blockDim.x + threadIdx.x;
    if (k < 1024) {
        float s, c;
        sincospif(-(float)k / 2048.0f, &s, &c);
        g_tw[k] = make_float2(c, s);
    }
    if (k == 0) {
        float b[E_NUM - 1];
        for (int i = 0; i < E_NUM - 1; i++) b[i] = 1.0f / (1.0f + expf(-raw[i]));
        for (int i = 1; i < E_NUM - 1; i++) {
            float v = b[i]; int j = i - 1;
            while (j >= 0 && b[j] > v) { b[j + 1] = b[j]; j--; }
            b[j + 1] = v;
        }
        float bd[E_NUM + 1];
        bd[0] = 0.f;
        for (int i = 0; i < E_NUM - 1; i++) bd[i + 1] = b[i];
        bd[E_NUM] = 1.f;
        for (int i = 0; i <= E_NUM; i++) {
            out_bounds[i] = bd[i];
            g_idx[i] = (int)floorf(bd[i] * (float)F_LEN);
        }
        g_idx[E_NUM] = F_LEN;
    }
}

// ---------------- kernel 1: norm + forward rfft via half-length trick ----------------
__global__ __launch_bounds__(NTF, 4) void k1_norm_fft(const float* __restrict__ x) {
    __shared__ float2 a[M_FFT];
    __shared__ float2 tw[1024];
    __shared__ float  red[16];

    int row = blockIdx.x;
    int tid = threadIdx.x;
    int lane = tid & 31, wid = tid >> 5;

    load_tw(tw, tid);

    const float4* xr = (const float4*)(x + (size_t)row * N_FFT);
    float s = 0.f, ss = 0.f;
    for (int i = tid; i < N_FFT / 4; i += NTF) {
        float4 v = xr[i];
        a[2 * i]     = make_float2(v.x, v.y);
        a[2 * i + 1] = make_float2(v.z, v.w);
        s  += (v.x + v.y) + (v.z + v.w);
        ss += v.x * v.x + v.y * v.y + v.z * v.z + v.w * v.w;
    }
    #pragma unroll
    for (int o = 16; o; o >>= 1) {
        s  += __shfl_xor_sync(0xffffffffu, s, o);
        ss += __shfl_xor_sync(0xffffffffu, ss, o);
    }
    if (lane == 0) { red[wid] = s; red[wid + 8] = ss; }
    __syncthreads();
    float sum = 0.f, sumsq = 0.f;
    #pragma unroll
    for (int i = 0; i < 8; i++) { sum += red[i]; sumsq += red[8 + i]; }

    float mean = sum * (1.0f / N_FFT);
    float var  = (sumsq - sum * mean) * (1.0f / (N_FFT - 1)) + 1e-5f;
    float stdv = sqrtf(var);
    float inv  = 1.0f / stdv;
    if (tid == 0) { g_mean[row] = mean; g_std[row] = stdv; }
    __syncthreads();

    // normalize + bit-reversal permutation (disjoint swap pairs)
    for (int n = tid; n < M_FFT; n += NTF) {
        int r = brev11(n);
        if (r > n) {
            float2 u = a[n], v = a[r];
            a[n] = make_float2((v.x - mean) * inv, (v.y - mean) * inv);
            a[r] = make_float2((u.x - mean) * inv, (u.y - mean) * inv);
        } else if (r == n) {
            float2 u = a[n];
            a[n] = make_float2((u.x - mean) * inv, (u.y - mean) * inv);
        }
    }
    __syncthreads();

    radix8_pass<0, false>(a, tw, tid); __syncthreads();
    radix8_pass<3, false>(a, tw, tid); __syncthreads();
    radix8_pass<6, false>(a, tw, tid); __syncthreads();
    radix4_final_smem<false>(a, tw, tid); __syncthreads();

    // unpack real-FFT halves
    float2* fr = g_freq + (size_t)row * F_LEN;
    for (int k = tid; k < M_FFT; k += NTF) {
        float2 Zk = a[k];
        float2 Zm = a[(M_FFT - k) & (M_FFT - 1)];
        float2 P = make_float2(Zk.x + Zm.x, Zk.y - Zm.y);
        float2 Q = make_float2(Zk.x - Zm.x, Zk.y + Zm.y);
        float2 w = w4096(tw, k);
        float2 t = cmul(w, Q);
        fr[k] = make_float2(0.5f * (P.x + t.y), 0.5f * (P.y - t.x));
    }
    if (tid == 0) fr[M_FFT] = make_float2(a[0].x - a[0].y, 0.f);
}

// ---------------- kernel 1b: gating input = mean_c |freq| ----------------
__global__ void k1b_gate() {
    int i = blockIdx.x * blockDim.x + threadIdx.x;
    if (i >= B_SZ * F_LEN) return;
    int b = i / F_LEN;
    int f = i - b * F_LEN;
    float acc = 0.f;
    #pragma unroll
    for (int c = 0; c < C_SZ; c++) {
        float2 v = g_freq[(size_t)(b * C_SZ + c) * F_LEN + f];
        acc += sqrtf(v.x * v.x + v.y * v.y);
    }
    g_gate[i] = acc * (1.0f / C_SZ);
}

// ---------------- kernel 2b: partial GEMM, O-tile 128, double-buffered ----------------
__global__ __launch_bounds__(256) void k2b_part(const float* __restrict__ W1) {
    __shared__ float Gs[2][32][33];     // [buf][b][kk]
    __shared__ float Ws[2][OTILE][33];  // [buf][o][kk]

    int t  = threadIdx.x;
    int tx = t & 31;            // o groups: o = oBase + tx + 32*j
    int ty = t >> 5;            // b groups: b = 4*ty + i
    int oBase = blockIdx.x * OTILE;
    int kBase = blockIdx.y * 64;

    float gr[4], wr[16];
    float acc[4][4] = {};

    // ---- load step 0 into regs
    {
        int k0 = kBase;
        #pragma unroll
        for (int i = 0; i < 4; i++) {
            int idx = t + i * 256, bb = idx >> 5, kk = idx & 31;
            gr[i] = (k0 + kk < F_LEN) ? g_gate[bb * F_LEN + k0 + kk] : 0.f;
        }
        #pragma unroll
        for (int i = 0; i < 16; i++) {
            int idx = t + i * 256, oo = idx >> 5, kk = idx & 31;
            int o = oBase + oo;
            wr[i] = (o < F_LEN && k0 + kk < F_LEN) ? W1[(size_t)o * F_LEN + k0 + kk] : 0.f;
        }
    }
    // ---- store step 0 to buf 0
    #pragma unroll
    for (int i = 0; i < 4; i++) {
        int idx = t + i * 256;
        Gs[0][idx >> 5][idx & 31] = gr[i];
    }
    #pragma unroll
    for (int i = 0; i < 16; i++) {
        int idx = t + i * 256;
        Ws[0][idx >> 5][idx & 31] = wr[i];
    }
    __syncthreads();

    // ---- issue loads for step 1 (overlap with compute of step 0)
    {
        int k0 = kBase + 32;
        #pragma unroll
        for (int i = 0; i < 4; i++) {
            int idx = t + i * 256, bb = idx >> 5, kk = idx & 31;
            gr[i] = (k0 + kk < F_LEN) ? g_gate[bb * F_LEN + k0 + kk] : 0.f;
        }
        #pragma unroll
        for (int i = 0; i < 16; i++) {
            int idx = t + i * 256, oo = idx >> 5, kk = idx & 31;
            int o = oBase + oo;
            wr[i] = (o < F_LEN && k0 + kk < F_LEN) ? W1[(size_t)o * F_LEN + k0 + kk] : 0.f;
        }
    }
    // ---- compute step 0
    #pragma unroll
    for (int kk = 0; kk < 32; kk++) {
        float g0 = Gs[0][4 * ty + 0][kk];
        float g1 = Gs[0][4 * ty + 1][kk];
        float g2 = Gs[0][4 * ty + 2][kk];
        float g3 = Gs[0][4 * ty + 3][kk];
        float w0 = Ws[0][tx][kk];
        float w1 = Ws[0][tx + 32][kk];
        float w2 = Ws[0][tx + 64][kk];
        float w3 = Ws[0][tx + 96][kk];
        acc[0][0] = fmaf(g0, w0, acc[0][0]); acc[0][1] = fmaf(g0, w1, acc[0][1]);
        acc[0][2] = fmaf(g0, w2, acc[0][2]); acc[0][3] = fmaf(g0, w3, acc[0][3]);
        acc[1][0] = fmaf(g1, w0, acc[1][0]); acc[1][1] = fmaf(g1, w1, acc[1][1]);
        acc[1][2] = fmaf(g1, w2, acc[1][2]); acc[1][3] = fmaf(g1, w3, acc[1][3]);
        acc[2][0] = fmaf(g2, w0, acc[2][0]); acc[2][1] = fmaf(g2, w1, acc[2][1]);
        acc[2][2] = fmaf(g2, w2, acc[2][2]); acc[2][3] = fmaf(g2, w3, acc[2][3]);
        acc[3][0] = fmaf(g3, w0, acc[3][0]); acc[3][1] = fmaf(g3, w1, acc[3][1]);
        acc[3][2] = fmaf(g3, w2, acc[3][2]); acc[3][3] = fmaf(g3, w3, acc[3][3]);
    }
    // ---- store step 1 to buf 1
    #pragma unroll
    for (int i = 0; i < 4; i++) {
        int idx = t + i * 256;
        Gs[1][idx >> 5][idx & 31] = gr[i];
    }
    #pragma unroll
    for (int i = 0; i < 16; i++) {
        int idx = t + i * 256;
        Ws[1][idx >> 5][idx & 31] = wr[i];
    }
    __syncthreads();

    // ---- compute step 1
    #pragma unroll
    for (int kk = 0; kk < 32; kk++) {
        float g0 = Gs[1][4 * ty + 0][kk];
        float g1 = Gs[1][4 * ty + 1][kk];
        float g2 = Gs[1][4 * ty + 2][kk];
        float g3 = Gs[1][4 * ty + 3][kk];
        float w0 = Ws[1][tx][kk];
        float w1 = Ws[1][tx + 32][kk];
        float w2 = Ws[1][tx + 64][kk];
        float w3 = Ws[1][tx + 96][kk];
        acc[0][0] = fmaf(g0, w0, acc[0][0]); acc[0][1] = fmaf(g0, w1, acc[0][1]);
        acc[0][2] = fmaf(g0, w2, acc[0][2]); acc[0][3] = fmaf(g0, w3, acc[0][3]);
        acc[1][0] = fmaf(g1, w0, acc[1][0]); acc[1][1] = fmaf(g1, w1, acc[1][1]);
        acc[1][2] = fmaf(g1, w2, acc[1][2]); acc[1][3] = fmaf(g1, w3, acc[1][3]);
        acc[2][0] = fmaf(g2, w0, acc[2][0]); acc[2][1] = fmaf(g2, w1, acc[2][1]);
        acc[2][2] = fmaf(g2, w2, acc[2][2]); acc[2][3] = fmaf(g2, w3, acc[2][3]);
        acc[3][0] = fmaf(g3, w0, acc[3][0]); acc[3][1] = fmaf(g3, w1, acc[3][1]);
        acc[3][2] = fmaf(g3, w2, acc[3][2]); acc[3][3] = fmaf(g3, w3, acc[3][3]);
    }

    #pragma unroll
    for (int i = 0; i < 4; i++)
        #pragma unroll
        for (int j = 0; j < 4; j++)
            g_part[blockIdx.y][4 * ty + i][oBase + tx + 32 * j] = acc[i][j];
}

// ---------------- kernel 2b-red: sum partials + bias + relu ----------------
__global__ void k2b_red(const float* __restrict__ b1) {
    int i = blockIdx.x * blockDim.x + threadIdx.x;
    if (i >= B_SZ * F_LEN) return;
    int b = i / F_LEN, o = i - b * F_LEN;
    float s = 0.f;
    #pragma unroll
    for (int ks = 0; ks < KSPL; ks++) s += g_part[ks][b][o];
    g_h[i] = fmaxf(s + b1[o], 0.f);
}

// ---------------- kernel 2c: logits + softmax ----------------
__global__ __launch_bounds__(256) void k2c_gate(const float* __restrict__ W2,
                                                const float* __restrict__ b2,
                                                float* __restrict__ out_scores) {
    __shared__ float red[256];
    __shared__ float logits[E_NUM];
    int b = blockIdx.x, tid = threadIdx.x;
    float acc[E_NUM];
    #pragma unroll
    for (int e = 0; e < E_NUM; e++) acc[e] = 0.f;
    for (int f = tid; f < F_LEN; f += 256) {
        float hv = g_h[b * F_LEN + f];
        #pragma unroll
        for (int e = 0; e < E_NUM; e++) acc[e] = fmaf(hv, W2[e * F_LEN + f], acc[e]);
    }
    for (int e = 0; e < E_NUM; e++) {
        red[tid] = acc[e]; __syncthreads();
        for (int o = 128; o > 0; o >>= 1) { if (tid < o) red[tid] += red[tid + o]; __syncthreads(); }
        if (tid == 0) logits[e] = red[0] + b2[e];
        __syncthreads();
    }
    if (tid == 0) {
        float mx = logits[0];
        for (int e = 1; e < E_NUM; e++) mx = fmaxf(mx, logits[e]);
        float sm = 0.f, ex[E_NUM];
        for (int e = 0; e < E_NUM; e++) { ex[e] = expf(logits[e] - mx); sm += ex[e]; }
        float is = 1.0f / sm;
        for (int e = 0; e < E_NUM; e++) {
            float v = ex[e] * is;
            g_scores[b * E_NUM + e] = v;
            out_scores[b * E_NUM + e] = v;
        }
    }
}

// spectrum prep for inverse half-length FFT
__device__ __forceinline__ float2 prep_band(const float2* __restrict__ fr,
                                            int k, int lo, int hi) {
    int km = M_FFT - k;
    float2 A = make_float2(0.f, 0.f), B = make_float2(0.f, 0.f);
    if (k >= lo && k < hi)   A = fr[k];
    if (km >= lo && km < hi) B = fr[km];
    float2 P  = make_float2(A.x + B.x, A.y - B.y);
    float2 Qw = make_float2(A.x - B.x, A.y + B.y);
    float2 w = w4096g(k);
    float2 cw = make_float2(w.x, -w.y);
    float2 Xo2 = cmul(Qw, cw);
    return make_float2(P.x - Xo2.y, P.y + Xo2.x);
}

// fused gather + first radix-8 (j=0, constant twiddles) for inverse kernels.
#define GATHER_RADIX8_INV(PREP)                                                   \
    {                                                                             \
        int base = (int)(__brev((unsigned)tid) >> 24);                            \
        float2 p0 = PREP(base);                                                   \
        float2 p1 = PREP(base + 1024);                                            \
        float2 p2 = PREP(base + 512);                                             \
        float2 p3 = PREP(base + 1536);                                            \
        float2 p4 = PREP(base + 256);                                             \
        float2 p5 = PREP(base + 1280);                                            \
        float2 p6 = PREP(base + 768);                                             \
        float2 p7 = PREP(base + 1792);                                            \
        bf1(p0, p1); bf1(p2, p3); bf1(p4, p5); bf1(p6, p7);                       \
        bf1(p0, p2);                                                              \
        { float2 t3 = make_float2(-p3.y, p3.x);                                   \
          float2 u = p1; p1 = make_float2(u.x + t3.x, u.y + t3.y);                \
          p3 = make_float2(u.x - t3.x, u.y - t3.y); }                             \
        bf1(p4, p6);                                                              \
        { float2 t7 = make_float2(-p7.y, p7.x);                                   \
          float2 u = p5; p5 = make_float2(u.x + t7.x, u.y + t7.y);                \
          p7 = make_float2(u.x - t7.x, u.y - t7.y); }                             \
        bf1(p0, p4);                                                              \
        bf(p1, p5, make_float2(RT2H, RT2H));                                      \
        { float2 t6 = make_float2(-p6.y, p6.x);                                   \
          float2 u = p2; p2 = make_float2(u.x + t6.x, u.y + t6.y);                \
          p6 = make_float2(u.x - t6.x, u.y - t6.y); }                             \
        bf(p3, p7, make_float2(-RT2H, RT2H));                                     \
        int o8 = tid * 8;                                                         \
        a[o8] = p0; a[o8 + 1] = p1; a[o8 + 2] = p2; a[o8 + 3] = p3;               \
        a[o8 + 4] = p4; a[o8 + 5] = p5; a[o8 + 6] = p6; a[o8 + 7] = p7;           \
    }

// ---------------- kernel 3: expert band irfft (radix-8, fully fused) ----------------
// out_exp has an ODD float offset -> scalar stores only.
__global__ __launch_bounds__(NTF, 4) void k3_expert(float* __restrict__ out_exp) {
    __shared__ float2 a[M_FFT];
    __shared__ float2 tw[1024];

    int blk = blockIdx.x;                 // b*64 + e*8 + c
    int c = blk & 7;
    int e = (blk >> 3) & 7;
    int b = blk >> 6;
    int row = b * C_SZ + c;
    int tid = threadIdx.x;

    int lo = g_idx[e], hi = g_idx[e + 1];
    load_tw(tw, tid);

    const float2* fr = g_freq + (size_t)row * F_LEN;

    #define PREP3(kk) prep_band(fr, (kk), lo, hi)
    GATHER_RADIX8_INV(PREP3)
    #undef PREP3
    __syncthreads();

    radix8_pass<3, true>(a, tw, tid); __syncthreads();
    radix8_pass<6, true>(a, tw, tid); __syncthreads();

    // final radix-4 fused with scaled scalar store
    float* o = out_exp + (size_t)blk * N_FFT;
    const float sc = 1.0f / (float)N_FFT;
    #pragma unroll
    for (int j = tid; j < 512; j += NTF) {
        float2 p0 = a[j], p1 = a[j + 512], p2 = a[j + 1024], p3 = a[j + 1536];
        float2 w1 = w4096(tw, j << 2);  w1.y = -w1.y;
        float2 w2 = w4096(tw, j << 1);  w2.y = -w2.y;
        bf(p0, p1, w1); bf(p2, p3, w1);
        float2 w2b = make_float2(-w2.y, w2.x);
        bf(p0, p2, w2); bf(p1, p3, w2b);
        o[2 * j]            = p0.x * sc;  o[2 * j + 1]            = p0.y * sc;
        o[2 * (j + 512)]    = p1.x * sc;  o[2 * (j + 512) + 1]    = p1.y * sc;
        o[2 * (j + 1024)]   = p2.x * sc;  o[2 * (j + 1024) + 1]   = p2.y * sc;
        o[2 * (j + 1536)]   = p3.x * sc;  o[2 * (j + 1536) + 1]   = p3.y * sc;
    }
}

// ---------------- kernel 4: gated combine irfft + denorm (radix-8 fused) ----------------
__device__ __forceinline__ float2 prep_gated(const float2* __restrict__ fr,
                                             int k, const int* s_idx, const float* s_g) {
    int km = M_FFT - k;
    int ea = 0, eb = 0;
    while (ea < E_NUM - 1 && k  >= s_idx[ea + 1]) ea++;
    while (eb < E_NUM - 1 && km >= s_idx[eb + 1]) eb++;
    float ga = s_g[ea], gb = s_g[eb];
    float2 Af = fr[k];
    float2 Bf = fr[km];
    float2 A = make_float2(Af.x * ga, Af.y * ga);
    float2 B = make_float2(Bf.x * gb, Bf.y * gb);
    float2 P  = make_float2(A.x + B.x, A.y - B.y);
    float2 Qw = make_float2(A.x - B.x, A.y + B.y);
    float2 w = w4096g(k);
    float2 cw = make_float2(w.x, -w.y);
    float2 Xo2 = cmul(Qw, cw);
    return make_float2(P.x - Xo2.y, P.y + Xo2.x);
}

__global__ __launch_bounds__(NTF, 4) void k4_combined(float* __restrict__ out_comb) {
    __shared__ float2 a[M_FFT];
    __shared__ float2 tw[1024];
    __shared__ int   s_idx[E_NUM + 1];
    __shared__ float s_g[E_NUM];

    int row = blockIdx.x;
    int b = row / C_SZ;
    int tid = threadIdx.x;

    if (tid < E_NUM + 1) s_idx[tid] = g_idx[tid];
    if (tid >= 32 && tid < 32 + E_NUM) s_g[tid - 32] = g_scores[b * E_NUM + (tid - 32)];
    load_tw(tw, tid);
    __syncthreads();

    const float2* fr = g_freq + (size_t)row * F_LEN;

    #define PREP4(kk) prep_gated(fr, (kk), s_idx, s_g)
    GATHER_RADIX8_INV(PREP4)
    #undef PREP4
    __syncthreads();

    radix8_pass<3, true>(a, tw, tid); __syncthreads();
    radix8_pass<6, true>(a, tw, tid); __syncthreads();

    float mean = g_mean[row], stdv = g_std[row];
    float2* o = (float2*)(out_comb + (size_t)row * N_FFT);   // 8B-aligned
    const float sc = 1.0f / (float)N_FFT;
    #pragma unroll
    for (int j = tid; j < 512; j += NTF) {
        float2 p0 = a[j], p1 = a[j + 512], p2 = a[j + 1024], p3 = a[j + 1536];
        float2 w1 = w4096(tw, j << 2);  w1.y = -w1.y;
        float2 w2 = w4096(tw, j << 1);  w2.y = -w2.y;
        bf(p0, p1, w1); bf(p2, p3, w1);
        float2 w2b = make_float2(-w2.y, w2.x);
        bf(p0, p2, w2); bf(p1, p3, w2b);
        o[j]        = make_float2(fmaf(p0.x * sc, stdv, mean), fmaf(p0.y * sc, stdv, mean));
        o[j + 512]  = make_float2(fmaf(p1.x * sc, stdv, mean), fmaf(p1.y * sc, stdv, mean));
        o[j + 1024] = make_float2(fmaf(p2.x * sc, stdv, mean), fmaf(p2.y * sc, stdv, mean));
        o[j + 1536] = make_float2(fmaf(p3.x * sc, stdv, mean), fmaf(p3.y * sc, stdv, mean));
    }
}

// ---------------- launch ----------------
extern "C" void kernel_launch(void* const* d_in, const int* in_sizes, int n_in,
                              void* d_out, int out_size) {
    const float* x   = (const float*)d_in[0];
    const float* raw = (const float*)d_in[1];
    const float* W1  = (const float*)d_in[2];
    const float* b1  = (const float*)d_in[3];
    const float* W2  = (const float*)d_in[4];
    const float* b2  = (const float*)d_in[5];
    float* out = (float*)d_out;

    const int comb_n   = B_SZ * C_SZ * N_FFT;
    const int bounds_n = E_NUM + 1;
    const int scores_n = B_SZ * E_NUM;
    const int exp_n    = B_SZ * E_NUM * C_SZ * N_FFT;
    const int total_n  = comb_n + bounds_n + scores_n + exp_n;

    bool full = (out_size >= total_n);

    float* out_comb = out;
    float* out_bounds;
    float* out_scores;
    float* out_exp = nullptr;

    if (full) {
        out_bounds = out + comb_n;
        out_scores = out_bounds + bounds_n;
        out_exp    = out_scores + scores_n;
    } else {
        cudaGetSymbolAddress((void**)&out_bounds, g_dummy);
        out_scores = out_bounds + 16;
    }

    k0_init<<<4, 256>>>(raw, out_bounds);
    k1_norm_fft<<<NROW, NTF>>>(x);
    k1b_gate<<<(B_SZ * F_LEN + 255) / 256, 256>>>();
    k2b_part<<<dim3(OBLK, KSPL), 256>>>(W1);
    k2b_red<<<(B_SZ * F_LEN + 255) / 256, 256>>>(b1);
    k2c_gate<<<B_SZ, 256>>>(W2, b2, out_scores);
    if (full) {
        k3_expert<<<B_SZ * E_NUM * C_SZ, NTF>>>(out_exp);
    }
    k4_combined<<<NROW, NTF>>>(out_comb);
}